// round 2
// baseline (speedup 1.0000x reference)
#include <cuda_runtime.h>
#include <cuda_bf16.h>

#define BB 4
#define NN 2048
#define HH 12
#define DD 64
#define CC 768

// ---- scratch (device globals: no allocations allowed) ----
__device__ float g_q[BB*HH*NN*DD];     // [B,H,N,D], pre-scaled by D^-0.5
__device__ float g_k[BB*HH*NN*DD];     // [B,H,N,D]
__device__ float g_v[BB*HH*NN*DD];     // [B,H,N,D]
__device__ float g_attn[BB*NN*HH*DD];  // [B,N,H,D] == [8192,768] row-major
__device__ unsigned char g_mask[BB*NN];

// ============================================================
// Mask canonicalization: detect whether the mask buffer is
// word-stride (int32 / float32 promoted bool) or byte-stride
// (bool8) and write canonical 0/1 bytes to g_mask.
// Pure function of input -> deterministic, graph-capturable.
// ============================================================
__global__ void mask_conv_kernel(const void* __restrict__ mraw)
{
    __shared__ int s_not_word;
    const int tid = threadIdx.x;
    if (tid == 0) s_not_word = 0;
    __syncthreads();

    const unsigned int* w = (const unsigned int*)mraw;
    // Inspect first 8192 bytes (= min possible buffer size) as 2048 words.
    for (int i = tid; i < 2048; i += blockDim.x) {
        unsigned int v = w[i];
        if (v != 0u && v != 1u && v != 0x3F800000u) atomicOr(&s_not_word, 1);
    }
    __syncthreads();

    const int wordlike = !s_not_word;
    const unsigned char* bptr = (const unsigned char*)mraw;
    for (int i = tid; i < BB * NN; i += blockDim.x) {
        unsigned char r;
        if (wordlike) r = (unsigned char)(w[i] != 0u);
        else          r = (unsigned char)(bptr[i] != 0);
        g_mask[i] = r;
    }
}

// ============================================================
// Tiled SGEMM: C[M,N] = A[M,K] @ W[K,N] + bias
// 128x128 tile, BK=8, 256 threads, 8x8 per thread.
// MODE 0: A = x, scatter into g_q/g_k/g_v (qkv epilogue)
// MODE 1: A = g_attn, write Cout (proj epilogue)
// ============================================================
template<int MODE>
__global__ __launch_bounds__(256) void gemm_k(
    const float* __restrict__ A, const float* __restrict__ W,
    const float* __restrict__ bias, float* __restrict__ Cout,
    int M, int K, int Nn)
{
    __shared__ float As[8][132];   // As[k][m] (transposed)
    __shared__ float Bs[8][132];   // Bs[k][n]
    const int tid = threadIdx.x;
    const int tx = tid & 15, ty = tid >> 4;
    const int bm = blockIdx.y * 128, bn = blockIdx.x * 128;
    const float* Ap = (MODE == 1) ? g_attn : A;

    float acc[8][8];
    #pragma unroll
    for (int i = 0; i < 8; i++)
        #pragma unroll
        for (int j = 0; j < 8; j++) acc[i][j] = 0.f;

    const int m_a = tid >> 1, k_a = (tid & 1) * 4;
    const int k_b = tid >> 5, n_b = (tid & 31) * 4;

    for (int k0 = 0; k0 < K; k0 += 8) {
        float4 av = *(const float4*)(Ap + (size_t)(bm + m_a) * K + (k0 + k_a));
        As[k_a + 0][m_a] = av.x;
        As[k_a + 1][m_a] = av.y;
        As[k_a + 2][m_a] = av.z;
        As[k_a + 3][m_a] = av.w;
        float4 bv = *(const float4*)(W + (size_t)(k0 + k_b) * Nn + (bn + n_b));
        *(float4*)&Bs[k_b][n_b] = bv;
        __syncthreads();

        #pragma unroll
        for (int kk = 0; kk < 8; kk++) {
            float4 a0 = *(const float4*)&As[kk][ty * 4];
            float4 a1 = *(const float4*)&As[kk][64 + ty * 4];
            float4 b0 = *(const float4*)&Bs[kk][tx * 4];
            float4 b1 = *(const float4*)&Bs[kk][64 + tx * 4];
            float a[8] = {a0.x, a0.y, a0.z, a0.w, a1.x, a1.y, a1.z, a1.w};
            float bb[8] = {b0.x, b0.y, b0.z, b0.w, b1.x, b1.y, b1.z, b1.w};
            #pragma unroll
            for (int i = 0; i < 8; i++)
                #pragma unroll
                for (int j = 0; j < 8; j++)
                    acc[i][j] += a[i] * bb[j];
        }
        __syncthreads();
    }

    #pragma unroll
    for (int i = 0; i < 8; i++) {
        int rr = bm + ((i < 4) ? (ty * 4 + i) : (64 + ty * 4 + i - 4));
        #pragma unroll
        for (int j = 0; j < 8; j++) {
            int cc = bn + ((j < 4) ? (tx * 4 + j) : (64 + tx * 4 + j - 4));
            float v = acc[i][j] + bias[cc];
            if (MODE == 0) {
                int which = cc / CC;
                int hc = cc - which * CC;
                int h = hc >> 6, d = hc & 63;
                int b = rr >> 11, n = rr & 2047;
                size_t off = ((size_t)((b * HH + h) * NN + n)) * DD + d;
                if (which == 0)      g_q[off] = v * 0.125f;  // fold in D^-0.5
                else if (which == 1) g_k[off] = v;
                else                 g_v[off] = v;
            } else {
                Cout[(size_t)rr * Nn + cc] = v;
            }
        }
    }
}

// ============================================================
// Fused flash-style attention.
// grid = (N/64, H, B); 256 threads; 64 query rows per CTA.
// Streams 64-key tiles: S = Q K^T + alibi, mask, online softmax, O += P V.
// ============================================================
#define SM_FLOATS (64*68 + 64*65 + 64*68 + 64*68 + 4*64)   // 17472
#define SM_BYTES  (SM_FLOATS * 4)                          // 69888

__global__ __launch_bounds__(256) void attn_kernel(
    const float* __restrict__ alibi)
{
    extern __shared__ float sm[];
    float* Qs   = sm;              // [i*68 + d]
    float* Kt   = Qs + 64 * 68;    // [d*65 + j]  (transposed)
    float* Vs   = Kt + 64 * 65;    // [j*68 + d]
    float* Ss   = Vs + 64 * 68;    // [i*68 + j]  (alibi -> scores -> probs)
    float* mrow = Ss + 64 * 68;    // running max
    float* lrow = mrow + 64;       // running sum
    float* frow = lrow + 64;       // rescale factor
    float* mkf  = frow + 64;       // key-mask for current tile

    const int tid = threadIdx.x;
    const int tx = tid & 15, ty = tid >> 4;
    const int qt = blockIdx.x, h = blockIdx.y, b = blockIdx.z;
    const int q0 = qt * 64;
    const int bh = b * HH + h;

    // load Q tile (already scaled)
    const float* Qg = g_q + ((size_t)(bh * NN + q0)) * DD;
    #pragma unroll
    for (int rr = 0; rr < 4; rr++) {
        int e = tid * 4 + rr * 1024;
        int i = e >> 6, d = e & 63;
        float4 v = *(const float4*)(Qg + i * 64 + d);
        *(float4*)&Qs[i * 68 + d] = v;
    }
    if (tid < 64) { mrow[tid] = -1e30f; lrow[tid] = 0.f; }

    float o[4][4];
    #pragma unroll
    for (int r = 0; r < 4; r++)
        #pragma unroll
        for (int c = 0; c < 4; c++) o[r][c] = 0.f;

    const size_t abase = ((size_t)bh * NN + q0) * NN;  // alibi[b,h,q0+i, :]

    for (int kt = 0; kt < 32; kt++) {
        const int kc0 = kt * 64;
        const float* Kg = g_k + ((size_t)(bh * NN + kc0)) * DD;
        const float* Vg = g_v + ((size_t)(bh * NN + kc0)) * DD;

        // load K (transposed), V, alibi tile (into Ss)
        #pragma unroll
        for (int rr = 0; rr < 4; rr++) {
            int e = tid * 4 + rr * 1024;
            int r0 = e >> 6, c0 = e & 63;
            float4 kv = *(const float4*)(Kg + r0 * 64 + c0);
            Kt[(c0 + 0) * 65 + r0] = kv.x;
            Kt[(c0 + 1) * 65 + r0] = kv.y;
            Kt[(c0 + 2) * 65 + r0] = kv.z;
            Kt[(c0 + 3) * 65 + r0] = kv.w;
            float4 vv = *(const float4*)(Vg + r0 * 64 + c0);
            *(float4*)&Vs[r0 * 68 + c0] = vv;
            float4 av = *(const float4*)(alibi + abase + (size_t)r0 * NN + kc0 + c0);
            *(float4*)&Ss[r0 * 68 + c0] = av;
        }
        if (tid < 64) mkf[tid] = g_mask[b * NN + kc0 + tid] ? 1.f : 0.f;
        __syncthreads();

        // S = Q K^T  (4x4 per thread)
        float s[4][4];
        #pragma unroll
        for (int r = 0; r < 4; r++)
            #pragma unroll
            for (int c = 0; c < 4; c++) s[r][c] = 0.f;

        #pragma unroll 16
        for (int d = 0; d < 64; d++) {
            float q0v = Qs[(ty * 4 + 0) * 68 + d];
            float q1v = Qs[(ty * 4 + 1) * 68 + d];
            float q2v = Qs[(ty * 4 + 2) * 68 + d];
            float q3v = Qs[(ty * 4 + 3) * 68 + d];
            float k0v = Kt[d * 65 + tx * 4 + 0];
            float k1v = Kt[d * 65 + tx * 4 + 1];
            float k2v = Kt[d * 65 + tx * 4 + 2];
            float k3v = Kt[d * 65 + tx * 4 + 3];
            s[0][0] += q0v * k0v; s[0][1] += q0v * k1v; s[0][2] += q0v * k2v; s[0][3] += q0v * k3v;
            s[1][0] += q1v * k0v; s[1][1] += q1v * k1v; s[1][2] += q1v * k2v; s[1][3] += q1v * k3v;
            s[2][0] += q2v * k0v; s[2][1] += q2v * k1v; s[2][2] += q2v * k2v; s[2][3] += q2v * k3v;
            s[3][0] += q3v * k0v; s[3][1] += q3v * k1v; s[3][2] += q3v * k2v; s[3][3] += q3v * k3v;
        }

        // + alibi (preloaded in Ss), apply key mask, write back to Ss
        #pragma unroll
        for (int r = 0; r < 4; r++) {
            int i = ty * 4 + r;
            float4 out4;
            float v0 = s[r][0] + Ss[i * 68 + tx * 4 + 0];
            float v1 = s[r][1] + Ss[i * 68 + tx * 4 + 1];
            float v2 = s[r][2] + Ss[i * 68 + tx * 4 + 2];
            float v3 = s[r][3] + Ss[i * 68 + tx * 4 + 3];
            out4.x = (mkf[tx * 4 + 0] != 0.f) ? -1e30f : v0;
            out4.y = (mkf[tx * 4 + 1] != 0.f) ? -1e30f : v1;
            out4.z = (mkf[tx * 4 + 2] != 0.f) ? -1e30f : v2;
            out4.w = (mkf[tx * 4 + 3] != 0.f) ? -1e30f : v3;
            *(float4*)&Ss[i * 68 + tx * 4] = out4;
        }
        __syncthreads();

        // online softmax: 4 lanes per row (row = tid/4, quarter = tid%4)
        {
            int r = tid >> 2, qq = tid & 3;
            int sb = r * 68 + qq * 16;
            float mt = -1e30f;
            #pragma unroll
            for (int jj = 0; jj < 16; jj++) mt = fmaxf(mt, Ss[sb + jj]);
            mt = fmaxf(mt, __shfl_xor_sync(0xffffffffu, mt, 1));
            mt = fmaxf(mt, __shfl_xor_sync(0xffffffffu, mt, 2));
            float mold = mrow[r];
            float mnew = fmaxf(mold, mt);
            float fac = __expf(mold - mnew);
            float ssum = 0.f;
            #pragma unroll
            for (int jj = 0; jj < 16; jj++) {
                float p = __expf(Ss[sb + jj] - mnew);
                Ss[sb + jj] = p;
                ssum += p;
            }
            ssum += __shfl_xor_sync(0xffffffffu, ssum, 1);
            ssum += __shfl_xor_sync(0xffffffffu, ssum, 2);
            if (qq == 0) {
                lrow[r] = lrow[r] * fac + ssum;
                mrow[r] = mnew;
                frow[r] = fac;
            }
        }
        __syncthreads();

        // rescale O, then O += P @ V
        #pragma unroll
        for (int r = 0; r < 4; r++) {
            float f = frow[ty * 4 + r];
            o[r][0] *= f; o[r][1] *= f; o[r][2] *= f; o[r][3] *= f;
        }
        #pragma unroll 8
        for (int j = 0; j < 64; j++) {
            float4 vv = *(const float4*)&Vs[j * 68 + tx * 4];
            #pragma unroll
            for (int r = 0; r < 4; r++) {
                float p = Ss[(ty * 4 + r) * 68 + j];
                o[r][0] += p * vv.x;
                o[r][1] += p * vv.y;
                o[r][2] += p * vv.z;
                o[r][3] += p * vv.w;
            }
        }
        __syncthreads();
    }

    // normalize and write [B,N,H,D]
    #pragma unroll
    for (int r = 0; r < 4; r++) {
        int i = ty * 4 + r;
        float inv = 1.0f / lrow[i];
        float4 ov = make_float4(o[r][0] * inv, o[r][1] * inv, o[r][2] * inv, o[r][3] * inv);
        size_t off = ((size_t)(b * NN + q0 + i) * HH + h) * DD + tx * 4;
        *(float4*)&g_attn[off] = ov;
    }
}

extern "C" void kernel_launch(void* const* d_in, const int* in_sizes, int n_in,
                              void* d_out, int out_size)
{
    // Identify inputs by element count (all distinct) — robust to ordering.
    const float* x      = nullptr;
    const void*  pmask  = nullptr;
    const float* alibi  = nullptr;
    const float* qkv_w  = nullptr;
    const float* qkv_b  = nullptr;
    const float* proj_w = nullptr;
    const float* proj_b = nullptr;
    for (int i = 0; i < n_in; i++) {
        switch (in_sizes[i]) {
            case 6291456:   x      = (const float*)d_in[i]; break;  // 4*2048*768
            case 8192:      pmask  = d_in[i];               break;  // 4*2048
            case 201326592: alibi  = (const float*)d_in[i]; break;  // 4*12*2048*2048
            case 1769472:   qkv_w  = (const float*)d_in[i]; break;  // 768*2304
            case 2304:      qkv_b  = (const float*)d_in[i]; break;
            case 589824:    proj_w = (const float*)d_in[i]; break;  // 768*768
            case 768:       proj_b = (const float*)d_in[i]; break;
        }
    }
    float* out = (float*)d_out;

    cudaFuncSetAttribute(attn_kernel,
                         cudaFuncAttributeMaxDynamicSharedMemorySize, SM_BYTES);

    // 0) canonicalize the padding mask (dtype-robust)
    mask_conv_kernel<<<1, 1024>>>(pmask);

    // 1) QKV projection: [8192,768] @ [768,2304] -> scatter Q/K/V
    gemm_k<0><<<dim3(2304 / 128, 8192 / 128), 256>>>(
        x, qkv_w, qkv_b, nullptr, BB * NN, CC, 3 * CC);

    // 2) fused attention
    attn_kernel<<<dim3(NN / 64, HH, BB), 256, SM_BYTES>>>(alibi);

    // 3) output projection: [8192,768] @ [768,768] -> d_out
    gemm_k<1><<<dim3(768 / 128, 8192 / 128), 256>>>(
        nullptr, proj_w, proj_b, out, BB * NN, CC, CC);
}

// round 4
// speedup vs baseline: 1.0001x; 1.0001x over previous
#include <cuda_runtime.h>
#include <cuda_bf16.h>

#define BB 4
#define NN 2048
#define HH 12
#define DD 64
#define CC 768

// ---- scratch (device globals: no allocations allowed) ----
__device__ float g_q[BB*HH*NN*DD];     // [B,H,N,D], pre-scaled by D^-0.5
__device__ float g_k[BB*HH*NN*DD];     // [B,H,N,D]
__device__ float g_v[BB*HH*NN*DD];     // [B,H,N,D]
__device__ float g_attn[BB*NN*HH*DD];  // [B,N,H,D] == [8192,768] row-major
__device__ unsigned char g_mask[BB*NN];

// ============================================================
// Mask canonicalization: detect whether the mask buffer is
// word-stride (int32 / float32 promoted bool) or byte-stride
// (bool8) and write canonical 0/1 bytes to g_mask.
// Pure function of input -> deterministic, graph-capturable.
// ============================================================
__global__ void mask_conv_kernel(const void* __restrict__ mraw)
{
    __shared__ int s_not_word;
    const int tid = threadIdx.x;
    if (tid == 0) s_not_word = 0;
    __syncthreads();

    const unsigned int* w = (const unsigned int*)mraw;
    // Inspect first 8192 bytes (= min possible buffer size) as 2048 words.
    for (int i = tid; i < 2048; i += blockDim.x) {
        unsigned int v = w[i];
        if (v != 0u && v != 1u && v != 0x3F800000u) atomicOr(&s_not_word, 1);
    }
    __syncthreads();

    const int wordlike = !s_not_word;
    const unsigned char* bptr = (const unsigned char*)mraw;
    for (int i = tid; i < BB * NN; i += blockDim.x) {
        unsigned char r;
        if (wordlike) r = (unsigned char)(w[i] != 0u);
        else          r = (unsigned char)(bptr[i] != 0);
        g_mask[i] = r;
    }
}

// ============================================================
// Tiled SGEMM: C[M,N] = A[M,K] @ W[K,N] + bias
// 128x128 tile, BK=8, 256 threads, 8x8 per thread.
// MODE 0: A = x, scatter into g_q/g_k/g_v (qkv epilogue)
// MODE 1: A = g_attn, write Cout (proj epilogue)
// ============================================================
template<int MODE>
__global__ __launch_bounds__(256) void gemm_k(
    const float* __restrict__ A, const float* __restrict__ W,
    const float* __restrict__ bias, float* __restrict__ Cout,
    int M, int K, int Nn)
{
    __shared__ float As[8][132];   // As[k][m] (transposed)
    __shared__ float Bs[8][132];   // Bs[k][n]
    const int tid = threadIdx.x;
    const int tx = tid & 15, ty = tid >> 4;
    const int bm = blockIdx.y * 128, bn = blockIdx.x * 128;
    const float* Ap = (MODE == 1) ? g_attn : A;

    float acc[8][8];
    #pragma unroll
    for (int i = 0; i < 8; i++)
        #pragma unroll
        for (int j = 0; j < 8; j++) acc[i][j] = 0.f;

    const int m_a = tid >> 1, k_a = (tid & 1) * 4;
    const int k_b = tid >> 5, n_b = (tid & 31) * 4;

    for (int k0 = 0; k0 < K; k0 += 8) {
        float4 av = *(const float4*)(Ap + (size_t)(bm + m_a) * K + (k0 + k_a));
        As[k_a + 0][m_a] = av.x;
        As[k_a + 1][m_a] = av.y;
        As[k_a + 2][m_a] = av.z;
        As[k_a + 3][m_a] = av.w;
        float4 bv = *(const float4*)(W + (size_t)(k0 + k_b) * Nn + (bn + n_b));
        *(float4*)&Bs[k_b][n_b] = bv;
        __syncthreads();

        #pragma unroll
        for (int kk = 0; kk < 8; kk++) {
            float4 a0 = *(const float4*)&As[kk][ty * 4];
            float4 a1 = *(const float4*)&As[kk][64 + ty * 4];
            float4 b0 = *(const float4*)&Bs[kk][tx * 4];
            float4 b1 = *(const float4*)&Bs[kk][64 + tx * 4];
            float a[8] = {a0.x, a0.y, a0.z, a0.w, a1.x, a1.y, a1.z, a1.w};
            float bb[8] = {b0.x, b0.y, b0.z, b0.w, b1.x, b1.y, b1.z, b1.w};
            #pragma unroll
            for (int i = 0; i < 8; i++)
                #pragma unroll
                for (int j = 0; j < 8; j++)
                    acc[i][j] += a[i] * bb[j];
        }
        __syncthreads();
    }

    #pragma unroll
    for (int i = 0; i < 8; i++) {
        int rr = bm + ((i < 4) ? (ty * 4 + i) : (64 + ty * 4 + i - 4));
        #pragma unroll
        for (int j = 0; j < 8; j++) {
            int cc = bn + ((j < 4) ? (tx * 4 + j) : (64 + tx * 4 + j - 4));
            float v = acc[i][j] + bias[cc];
            if (MODE == 0) {
                int which = cc / CC;
                int hc = cc - which * CC;
                int h = hc >> 6, d = hc & 63;
                int b = rr >> 11, n = rr & 2047;
                size_t off = ((size_t)((b * HH + h) * NN + n)) * DD + d;
                if (which == 0)      g_q[off] = v * 0.125f;  // fold in D^-0.5
                else if (which == 1) g_k[off] = v;
                else                 g_v[off] = v;
            } else {
                Cout[(size_t)rr * Nn + cc] = v;
            }
        }
    }
}

// ============================================================
// Fused flash-style attention.
// grid = (N/64, H, B); 256 threads; 64 query rows per CTA.
// Streams 64-key tiles: S = Q K^T + alibi, mask, online softmax, O += P V.
// ============================================================
#define SM_FLOATS (64*68 + 64*65 + 64*68 + 64*68 + 4*64)   // 17472
#define SM_BYTES  (SM_FLOATS * 4)                          // 69888

__global__ __launch_bounds__(256) void attn_kernel(
    const float* __restrict__ alibi)
{
    extern __shared__ float sm[];
    float* Qs   = sm;              // [i*68 + d]
    float* Kt   = Qs + 64 * 68;    // [d*65 + j]  (transposed)
    float* Vs   = Kt + 64 * 65;    // [j*68 + d]
    float* Ss   = Vs + 64 * 68;    // [i*68 + j]  (alibi -> scores -> probs)
    float* mrow = Ss + 64 * 68;    // running max
    float* lrow = mrow + 64;       // running sum
    float* frow = lrow + 64;       // rescale factor
    float* mkf  = frow + 64;       // key-mask for current tile

    const int tid = threadIdx.x;
    const int tx = tid & 15, ty = tid >> 4;
    const int qt = blockIdx.x, h = blockIdx.y, b = blockIdx.z;
    const int q0 = qt * 64;
    const int bh = b * HH + h;

    // load Q tile (already scaled)
    const float* Qg = g_q + ((size_t)(bh * NN + q0)) * DD;
    #pragma unroll
    for (int rr = 0; rr < 4; rr++) {
        int e = tid * 4 + rr * 1024;
        int i = e >> 6, d = e & 63;
        float4 v = *(const float4*)(Qg + i * 64 + d);
        *(float4*)&Qs[i * 68 + d] = v;
    }
    if (tid < 64) { mrow[tid] = -1e30f; lrow[tid] = 0.f; }

    float o[4][4];
    #pragma unroll
    for (int r = 0; r < 4; r++)
        #pragma unroll
        for (int c = 0; c < 4; c++) o[r][c] = 0.f;

    const size_t abase = ((size_t)bh * NN + q0) * NN;  // alibi[b,h,q0+i, :]

    for (int kt = 0; kt < 32; kt++) {
        const int kc0 = kt * 64;
        const float* Kg = g_k + ((size_t)(bh * NN + kc0)) * DD;
        const float* Vg = g_v + ((size_t)(bh * NN + kc0)) * DD;

        // load K (transposed), V, alibi tile (into Ss)
        #pragma unroll
        for (int rr = 0; rr < 4; rr++) {
            int e = tid * 4 + rr * 1024;
            int r0 = e >> 6, c0 = e & 63;
            float4 kv = *(const float4*)(Kg + r0 * 64 + c0);
            Kt[(c0 + 0) * 65 + r0] = kv.x;
            Kt[(c0 + 1) * 65 + r0] = kv.y;
            Kt[(c0 + 2) * 65 + r0] = kv.z;
            Kt[(c0 + 3) * 65 + r0] = kv.w;
            float4 vv = *(const float4*)(Vg + r0 * 64 + c0);
            *(float4*)&Vs[r0 * 68 + c0] = vv;
            float4 av = *(const float4*)(alibi + abase + (size_t)r0 * NN + kc0 + c0);
            *(float4*)&Ss[r0 * 68 + c0] = av;
        }
        if (tid < 64) mkf[tid] = g_mask[b * NN + kc0 + tid] ? 1.f : 0.f;
        __syncthreads();

        // S = Q K^T  (4x4 per thread)
        float s[4][4];
        #pragma unroll
        for (int r = 0; r < 4; r++)
            #pragma unroll
            for (int c = 0; c < 4; c++) s[r][c] = 0.f;

        #pragma unroll 16
        for (int d = 0; d < 64; d++) {
            float q0v = Qs[(ty * 4 + 0) * 68 + d];
            float q1v = Qs[(ty * 4 + 1) * 68 + d];
            float q2v = Qs[(ty * 4 + 2) * 68 + d];
            float q3v = Qs[(ty * 4 + 3) * 68 + d];
            float k0v = Kt[d * 65 + tx * 4 + 0];
            float k1v = Kt[d * 65 + tx * 4 + 1];
            float k2v = Kt[d * 65 + tx * 4 + 2];
            float k3v = Kt[d * 65 + tx * 4 + 3];
            s[0][0] += q0v * k0v; s[0][1] += q0v * k1v; s[0][2] += q0v * k2v; s[0][3] += q0v * k3v;
            s[1][0] += q1v * k0v; s[1][1] += q1v * k1v; s[1][2] += q1v * k2v; s[1][3] += q1v * k3v;
            s[2][0] += q2v * k0v; s[2][1] += q2v * k1v; s[2][2] += q2v * k2v; s[2][3] += q2v * k3v;
            s[3][0] += q3v * k0v; s[3][1] += q3v * k1v; s[3][2] += q3v * k2v; s[3][3] += q3v * k3v;
        }

        // + alibi (preloaded in Ss), apply key mask, write back to Ss
        #pragma unroll
        for (int r = 0; r < 4; r++) {
            int i = ty * 4 + r;
            float4 out4;
            float v0 = s[r][0] + Ss[i * 68 + tx * 4 + 0];
            float v1 = s[r][1] + Ss[i * 68 + tx * 4 + 1];
            float v2 = s[r][2] + Ss[i * 68 + tx * 4 + 2];
            float v3 = s[r][3] + Ss[i * 68 + tx * 4 + 3];
            out4.x = (mkf[tx * 4 + 0] != 0.f) ? -1e30f : v0;
            out4.y = (mkf[tx * 4 + 1] != 0.f) ? -1e30f : v1;
            out4.z = (mkf[tx * 4 + 2] != 0.f) ? -1e30f : v2;
            out4.w = (mkf[tx * 4 + 3] != 0.f) ? -1e30f : v3;
            *(float4*)&Ss[i * 68 + tx * 4] = out4;
        }
        __syncthreads();

        // online softmax: 4 lanes per row (row = tid/4, quarter = tid%4)
        {
            int r = tid >> 2, qq = tid & 3;
            int sb = r * 68 + qq * 16;
            float mt = -1e30f;
            #pragma unroll
            for (int jj = 0; jj < 16; jj++) mt = fmaxf(mt, Ss[sb + jj]);
            mt = fmaxf(mt, __shfl_xor_sync(0xffffffffu, mt, 1));
            mt = fmaxf(mt, __shfl_xor_sync(0xffffffffu, mt, 2));
            float mold = mrow[r];
            float mnew = fmaxf(mold, mt);
            float fac = __expf(mold - mnew);
            float ssum = 0.f;
            #pragma unroll
            for (int jj = 0; jj < 16; jj++) {
                float p = __expf(Ss[sb + jj] - mnew);
                Ss[sb + jj] = p;
                ssum += p;
            }
            ssum += __shfl_xor_sync(0xffffffffu, ssum, 1);
            ssum += __shfl_xor_sync(0xffffffffu, ssum, 2);
            if (qq == 0) {
                lrow[r] = lrow[r] * fac + ssum;
                mrow[r] = mnew;
                frow[r] = fac;
            }
        }
        __syncthreads();

        // rescale O, then O += P @ V
        #pragma unroll
        for (int r = 0; r < 4; r++) {
            float f = frow[ty * 4 + r];
            o[r][0] *= f; o[r][1] *= f; o[r][2] *= f; o[r][3] *= f;
        }
        #pragma unroll 8
        for (int j = 0; j < 64; j++) {
            float4 vv = *(const float4*)&Vs[j * 68 + tx * 4];
            #pragma unroll
            for (int r = 0; r < 4; r++) {
                float p = Ss[(ty * 4 + r) * 68 + j];
                o[r][0] += p * vv.x;
                o[r][1] += p * vv.y;
                o[r][2] += p * vv.z;
                o[r][3] += p * vv.w;
            }
        }
        __syncthreads();
    }

    // normalize and write [B,N,H,D]
    #pragma unroll
    for (int r = 0; r < 4; r++) {
        int i = ty * 4 + r;
        float inv = 1.0f / lrow[i];
        float4 ov = make_float4(o[r][0] * inv, o[r][1] * inv, o[r][2] * inv, o[r][3] * inv);
        size_t off = ((size_t)(b * NN + q0 + i) * HH + h) * DD + tx * 4;
        *(float4*)&g_attn[off] = ov;
    }
}

extern "C" void kernel_launch(void* const* d_in, const int* in_sizes, int n_in,
                              void* d_out, int out_size)
{
    // Identify inputs by element count (all distinct) — robust to ordering.
    const float* x      = nullptr;
    const void*  pmask  = nullptr;
    const float* alibi  = nullptr;
    const float* qkv_w  = nullptr;
    const float* qkv_b  = nullptr;
    const float* proj_w = nullptr;
    const float* proj_b = nullptr;
    for (int i = 0; i < n_in; i++) {
        switch (in_sizes[i]) {
            case 6291456:   x      = (const float*)d_in[i]; break;  // 4*2048*768
            case 8192:      pmask  = d_in[i];               break;  // 4*2048
            case 201326592: alibi  = (const float*)d_in[i]; break;  // 4*12*2048*2048
            case 1769472:   qkv_w  = (const float*)d_in[i]; break;  // 768*2304
            case 2304:      qkv_b  = (const float*)d_in[i]; break;
            case 589824:    proj_w = (const float*)d_in[i]; break;  // 768*768
            case 768:       proj_b = (const float*)d_in[i]; break;
        }
    }
    float* out = (float*)d_out;

    cudaFuncSetAttribute(attn_kernel,
                         cudaFuncAttributeMaxDynamicSharedMemorySize, SM_BYTES);

    // 0) canonicalize the padding mask (dtype-robust)
    mask_conv_kernel<<<1, 1024>>>(pmask);

    // 1) QKV projection: [8192,768] @ [768,2304] -> scatter Q/K/V
    gemm_k<0><<<dim3(2304 / 128, 8192 / 128), 256>>>(
        x, qkv_w, qkv_b, nullptr, BB * NN, CC, 3 * CC);

    // 2) fused attention
    attn_kernel<<<dim3(NN / 64, HH, BB), 256, SM_BYTES>>>(alibi);

    // 3) output projection: [8192,768] @ [768,768] -> d_out
    gemm_k<1><<<dim3(768 / 128, 8192 / 128), 256>>>(
        nullptr, proj_w, proj_b, out, BB * NN, CC, CC);
}

// round 5
// speedup vs baseline: 2.1682x; 2.1679x over previous
#include <cuda_runtime.h>
#include <cuda_bf16.h>
#include <cstdint>

#define BB 4
#define NN 2048
#define HH 12
#define DD 64
#define CC 768

// ---- scratch (device globals: no allocations allowed) ----
__device__ float g_q[BB*HH*NN*DD];     // [B,H,N,D], pre-scaled by D^-0.5
__device__ float g_k[BB*HH*NN*DD];     // [B,H,N,D]
__device__ float g_v[BB*HH*NN*DD];     // [B,H,N,D]
__device__ float g_attn[BB*NN*HH*DD];  // [B,N,H,D] == [8192,768] row-major
__device__ unsigned char g_mask[BB*NN];

// ---- tf32 helpers ----
__device__ __forceinline__ uint32_t f2tf(float f) {
    uint32_t u;
    asm("cvt.rna.tf32.f32 %0, %1;" : "=r"(u) : "f"(f));
    return u;
}
__device__ __forceinline__ void mma8(float* c, const uint32_t* a, const uint32_t* b) {
    asm volatile(
        "mma.sync.aligned.m16n8k8.row.col.f32.tf32.tf32.f32 "
        "{%0,%1,%2,%3},{%4,%5,%6,%7},{%8,%9},{%0,%1,%2,%3};"
        : "+f"(c[0]), "+f"(c[1]), "+f"(c[2]), "+f"(c[3])
        : "r"(a[0]), "r"(a[1]), "r"(a[2]), "r"(a[3]), "r"(b[0]), "r"(b[1]));
}

// ============================================================
// Mask canonicalization (dtype-robust, deterministic).
// ============================================================
__global__ void mask_conv_kernel(const void* __restrict__ mraw)
{
    __shared__ int s_not_word;
    const int tid = threadIdx.x;
    if (tid == 0) s_not_word = 0;
    __syncthreads();

    const unsigned int* w = (const unsigned int*)mraw;
    for (int i = tid; i < 2048; i += blockDim.x) {
        unsigned int v = w[i];
        if (v != 0u && v != 1u && v != 0x3F800000u) atomicOr(&s_not_word, 1);
    }
    __syncthreads();

    const int wordlike = !s_not_word;
    const unsigned char* bptr = (const unsigned char*)mraw;
    for (int i = tid; i < BB * NN; i += blockDim.x) {
        unsigned char r;
        if (wordlike) r = (unsigned char)(w[i] != 0u);
        else          r = (unsigned char)(bptr[i] != 0);
        g_mask[i] = r;
    }
}

// ============================================================
// tf32 tensor-core GEMM: C[M,N] = A[M,K] @ W[K,N] + bias
// 128x128x16 tiles, 256 threads (8 warps), warp tile 64x32,
// m16n8k8 frags 4x4 per warp. Register-prefetch pipeline.
// MODE 0: A = x, scatter into g_q/g_k/g_v
// MODE 1: A = g_attn, write Cout
// ============================================================
#define SG 136   // smem row stride (conflict-free frag gathers)

template<int MODE>
__global__ __launch_bounds__(256) void gemm_k(
    const float* __restrict__ A, const float* __restrict__ W,
    const float* __restrict__ bias, float* __restrict__ Cout,
    int M, int K, int Nn)
{
    __shared__ uint32_t As[16][SG];   // [k][m] tf32
    __shared__ uint32_t Bs[16][SG];   // [k][n] tf32

    const int tid = threadIdx.x, lane = tid & 31, w = tid >> 5;
    const int wm = w >> 2, wn = w & 3;         // warp grid 2x4
    const int lr = lane >> 2, lq = lane & 3;
    const int bm = blockIdx.y * 128, bn = blockIdx.x * 128;
    const float* Ap = (MODE == 1) ? g_attn : A;

    const int m_a = tid >> 1, k_a = (tid & 1) * 8;   // A tile loader
    const int k_b = tid >> 5, n_b = (tid & 31) * 4;  // B tile loader (rows k_b, k_b+8)

    float acc[4][4][4];
    #pragma unroll
    for (int i = 0; i < 4; i++)
        #pragma unroll
        for (int j = 0; j < 4; j++)
            #pragma unroll
            for (int e = 0; e < 4; e++) acc[i][j][e] = 0.f;

    float4 pa0, pa1, pb0, pb1;

    // prefetch tile 0 into regs
    {
        const float* ap = Ap + (size_t)(bm + m_a) * K + k_a;
        pa0 = *(const float4*)(ap);
        pa1 = *(const float4*)(ap + 4);
        pb0 = *(const float4*)(W + (size_t)(k_b)     * Nn + bn + n_b);
        pb1 = *(const float4*)(W + (size_t)(k_b + 8) * Nn + bn + n_b);
    }
    // store tile 0
    {
        As[k_a + 0][m_a] = f2tf(pa0.x); As[k_a + 1][m_a] = f2tf(pa0.y);
        As[k_a + 2][m_a] = f2tf(pa0.z); As[k_a + 3][m_a] = f2tf(pa0.w);
        As[k_a + 4][m_a] = f2tf(pa1.x); As[k_a + 5][m_a] = f2tf(pa1.y);
        As[k_a + 6][m_a] = f2tf(pa1.z); As[k_a + 7][m_a] = f2tf(pa1.w);
        uint4 u0 = make_uint4(f2tf(pb0.x), f2tf(pb0.y), f2tf(pb0.z), f2tf(pb0.w));
        uint4 u1 = make_uint4(f2tf(pb1.x), f2tf(pb1.y), f2tf(pb1.z), f2tf(pb1.w));
        *(uint4*)&Bs[k_b][n_b]     = u0;
        *(uint4*)&Bs[k_b + 8][n_b] = u1;
    }
    __syncthreads();

    for (int k0 = 0; k0 < K; k0 += 16) {
        const bool more = (k0 + 16 < K);
        if (more) {
            const float* ap = Ap + (size_t)(bm + m_a) * K + (k0 + 16 + k_a);
            pa0 = *(const float4*)(ap);
            pa1 = *(const float4*)(ap + 4);
            pb0 = *(const float4*)(W + (size_t)(k0 + 16 + k_b)     * Nn + bn + n_b);
            pb1 = *(const float4*)(W + (size_t)(k0 + 16 + k_b + 8) * Nn + bn + n_b);
        }

        #pragma unroll
        for (int ks = 0; ks < 16; ks += 8) {
            uint32_t a[4][4], bb[4][2];
            #pragma unroll
            for (int mf = 0; mf < 4; mf++) {
                int r = wm * 64 + mf * 16;
                a[mf][0] = As[ks + lq    ][r + lr];
                a[mf][1] = As[ks + lq    ][r + lr + 8];
                a[mf][2] = As[ks + lq + 4][r + lr];
                a[mf][3] = As[ks + lq + 4][r + lr + 8];
            }
            #pragma unroll
            for (int nf = 0; nf < 4; nf++) {
                int c = wn * 32 + nf * 8;
                bb[nf][0] = Bs[ks + lq    ][c + lr];
                bb[nf][1] = Bs[ks + lq + 4][c + lr];
            }
            #pragma unroll
            for (int mf = 0; mf < 4; mf++)
                #pragma unroll
                for (int nf = 0; nf < 4; nf++)
                    mma8(acc[mf][nf], a[mf], bb[nf]);
        }
        __syncthreads();

        if (more) {
            As[k_a + 0][m_a] = f2tf(pa0.x); As[k_a + 1][m_a] = f2tf(pa0.y);
            As[k_a + 2][m_a] = f2tf(pa0.z); As[k_a + 3][m_a] = f2tf(pa0.w);
            As[k_a + 4][m_a] = f2tf(pa1.x); As[k_a + 5][m_a] = f2tf(pa1.y);
            As[k_a + 6][m_a] = f2tf(pa1.z); As[k_a + 7][m_a] = f2tf(pa1.w);
            uint4 u0 = make_uint4(f2tf(pb0.x), f2tf(pb0.y), f2tf(pb0.z), f2tf(pb0.w));
            uint4 u1 = make_uint4(f2tf(pb1.x), f2tf(pb1.y), f2tf(pb1.z), f2tf(pb1.w));
            *(uint4*)&Bs[k_b][n_b]     = u0;
            *(uint4*)&Bs[k_b + 8][n_b] = u1;
            __syncthreads();
        }
    }

    // epilogue: acc element e -> (row = +8 if e>=2, col = +1 if e&1)
    #pragma unroll
    for (int mf = 0; mf < 4; mf++) {
        #pragma unroll
        for (int nf = 0; nf < 4; nf++) {
            #pragma unroll
            for (int e = 0; e < 4; e++) {
                int rr = bm + wm * 64 + mf * 16 + lr + ((e >= 2) ? 8 : 0);
                int cc = bn + wn * 32 + nf * 8 + 2 * lq + (e & 1);
                float v = acc[mf][nf][e] + bias[cc];
                if (MODE == 0) {
                    int which = cc / CC;
                    int hc = cc - which * CC;
                    int hh = hc >> 6, d = hc & 63;
                    int b = rr >> 11, n = rr & 2047;
                    size_t off = ((size_t)((b * HH + hh) * NN + n)) * DD + d;
                    if (which == 0)      g_q[off] = v * 0.125f;
                    else if (which == 1) g_k[off] = v;
                    else                 g_v[off] = v;
                } else {
                    Cout[(size_t)rr * Nn + cc] = v;
                }
            }
        }
    }
}

// ============================================================
// Fused flash attention with tf32 tensor cores.
// grid = (N/64, H, B); 256 threads (8 warps); 64 q-rows per CTA.
// Warp grid 2x4 over (64q x 64): warp tile 32x16, m16n8k8 frags 2x2.
// ============================================================
#define SA 76   // stride for Qs/Ks/Ss (conflict-free)
#define SV 72   // stride for Vs (conflict-free)
#define SM_FLOATS (64*SA*3 + 64*SV + 4*64)
#define SM_BYTES  (SM_FLOATS * 4)

__global__ __launch_bounds__(256) void attn_kernel(
    const float* __restrict__ alibi)
{
    extern __shared__ float sm[];
    uint32_t* Qs = (uint32_t*)sm;            // [64][SA] tf32 (pre-scaled)
    uint32_t* Ks = Qs + 64 * SA;             // [64][SA] tf32  Ks[key][d]
    uint32_t* Vs = Ks + 64 * SA;             // [64][SV] tf32  Vs[key][d]
    float*    Ss = (float*)(Vs + 64 * SV);   // [64][SA] alibi -> scores -> probs
    float* mrow = Ss + 64 * SA;
    float* lrow = mrow + 64;
    float* frow = lrow + 64;
    float* mkf  = frow + 64;

    const int tid = threadIdx.x, lane = tid & 31, w = tid >> 5;
    const int wm = w >> 2, wn = w & 3;       // 2 x 4
    const int lr = lane >> 2, lq = lane & 3;
    const int qt = blockIdx.x, h = blockIdx.y, b = blockIdx.z;
    const int q0 = qt * 64;
    const int bh = b * HH + h;
    const int rm = wm * 32;                  // warp q-row base
    const int cn = wn * 16;                  // warp key/d-col base

    // load Q tile (convert to tf32)
    const float* Qg = g_q + ((size_t)(bh * NN + q0)) * DD;
    #pragma unroll
    for (int rr2 = 0; rr2 < 4; rr2++) {
        int e = tid * 4 + rr2 * 1024;
        int i = e >> 6, d = e & 63;
        float4 v = *(const float4*)(Qg + i * 64 + d);
        uint4 u = make_uint4(f2tf(v.x), f2tf(v.y), f2tf(v.z), f2tf(v.w));
        *(uint4*)&Qs[i * SA + d] = u;
    }
    if (tid < 64) { mrow[tid] = -1e30f; lrow[tid] = 0.f; }

    float oacc[2][2][4];
    #pragma unroll
    for (int i = 0; i < 2; i++)
        #pragma unroll
        for (int j = 0; j < 2; j++)
            #pragma unroll
            for (int e = 0; e < 4; e++) oacc[i][j][e] = 0.f;

    const size_t abase = ((size_t)bh * NN + q0) * NN;

    for (int kt = 0; kt < 32; kt++) {
        __syncthreads();   // Q ready (kt=0) / prev PV reads done
        const int kc0 = kt * 64;
        const float* Kg = g_k + ((size_t)(bh * NN + kc0)) * DD;
        const float* Vg = g_v + ((size_t)(bh * NN + kc0)) * DD;

        #pragma unroll
        for (int rr2 = 0; rr2 < 4; rr2++) {
            int e = tid * 4 + rr2 * 1024;
            int r0 = e >> 6, c0 = e & 63;
            float4 kv = *(const float4*)(Kg + r0 * 64 + c0);
            *(uint4*)&Ks[r0 * SA + c0] =
                make_uint4(f2tf(kv.x), f2tf(kv.y), f2tf(kv.z), f2tf(kv.w));
            float4 vv = *(const float4*)(Vg + r0 * 64 + c0);
            *(uint4*)&Vs[r0 * SV + c0] =
                make_uint4(f2tf(vv.x), f2tf(vv.y), f2tf(vv.z), f2tf(vv.w));
            float4 av = *(const float4*)(alibi + abase + (size_t)r0 * NN + kc0 + c0);
            *(float4*)&Ss[r0 * SA + c0] = av;
        }
        if (tid < 64) mkf[tid] = g_mask[b * NN + kc0 + tid] ? 1.f : 0.f;
        __syncthreads();

        // ---- S = Q @ K^T (tensor core) ----
        float sacc[2][2][4];
        #pragma unroll
        for (int i = 0; i < 2; i++)
            #pragma unroll
            for (int j = 0; j < 2; j++)
                #pragma unroll
                for (int e = 0; e < 4; e++) sacc[i][j][e] = 0.f;

        #pragma unroll
        for (int kc = 0; kc < 64; kc += 8) {
            uint32_t a[2][4], bf[2][2];
            #pragma unroll
            for (int mf = 0; mf < 2; mf++) {
                int r = rm + mf * 16;
                a[mf][0] = Qs[(r + lr    ) * SA + kc + lq];
                a[mf][1] = Qs[(r + lr + 8) * SA + kc + lq];
                a[mf][2] = Qs[(r + lr    ) * SA + kc + lq + 4];
                a[mf][3] = Qs[(r + lr + 8) * SA + kc + lq + 4];
            }
            #pragma unroll
            for (int nf = 0; nf < 2; nf++) {
                int c = cn + nf * 8;
                bf[nf][0] = Ks[(c + lr) * SA + kc + lq];
                bf[nf][1] = Ks[(c + lr) * SA + kc + lq + 4];
            }
            #pragma unroll
            for (int mf = 0; mf < 2; mf++)
                #pragma unroll
                for (int nf = 0; nf < 2; nf++)
                    mma8(sacc[mf][nf], a[mf], bf[nf]);
        }

        // ---- + alibi, mask, write scores to Ss ----
        #pragma unroll
        for (int mf = 0; mf < 2; mf++) {
            int q = rm + mf * 16 + lr;
            #pragma unroll
            for (int nf = 0; nf < 2; nf++) {
                int c = cn + nf * 8 + 2 * lq;
                float m0 = mkf[c], m1 = mkf[c + 1];
                int i0 = q * SA + c, i1 = (q + 8) * SA + c;
                float v0 = sacc[mf][nf][0] + Ss[i0];
                float v1 = sacc[mf][nf][1] + Ss[i0 + 1];
                float v2 = sacc[mf][nf][2] + Ss[i1];
                float v3 = sacc[mf][nf][3] + Ss[i1 + 1];
                Ss[i0]     = (m0 != 0.f) ? -1e30f : v0;
                Ss[i0 + 1] = (m1 != 0.f) ? -1e30f : v1;
                Ss[i1]     = (m0 != 0.f) ? -1e30f : v2;
                Ss[i1 + 1] = (m1 != 0.f) ? -1e30f : v3;
            }
        }
        __syncthreads();

        // ---- online softmax: 4 lanes per row ----
        {
            int r = tid >> 2, qq = tid & 3;
            int sb = r * SA + qq * 16;
            float mt = -1e30f;
            #pragma unroll
            for (int jj = 0; jj < 16; jj++) mt = fmaxf(mt, Ss[sb + jj]);
            mt = fmaxf(mt, __shfl_xor_sync(0xffffffffu, mt, 1));
            mt = fmaxf(mt, __shfl_xor_sync(0xffffffffu, mt, 2));
            float mold = mrow[r];
            float mnew = fmaxf(mold, mt);
            float fac = __expf(mold - mnew);
            float ssum = 0.f;
            #pragma unroll
            for (int jj = 0; jj < 16; jj++) {
                float p = __expf(Ss[sb + jj] - mnew);
                Ss[sb + jj] = p;
                ssum += p;
            }
            ssum += __shfl_xor_sync(0xffffffffu, ssum, 1);
            ssum += __shfl_xor_sync(0xffffffffu, ssum, 2);
            if (qq == 0) {
                lrow[r] = lrow[r] * fac + ssum;
                mrow[r] = mnew;
                frow[r] = fac;
            }
        }
        __syncthreads();

        // ---- rescale O, then O += P @ V (tensor core) ----
        #pragma unroll
        for (int mf = 0; mf < 2; mf++) {
            float f0 = frow[rm + mf * 16 + lr];
            float f1 = frow[rm + mf * 16 + lr + 8];
            #pragma unroll
            for (int nf = 0; nf < 2; nf++) {
                oacc[mf][nf][0] *= f0; oacc[mf][nf][1] *= f0;
                oacc[mf][nf][2] *= f1; oacc[mf][nf][3] *= f1;
            }
        }
        #pragma unroll
        for (int kc = 0; kc < 64; kc += 8) {
            uint32_t a[2][4], bf[2][2];
            #pragma unroll
            for (int mf = 0; mf < 2; mf++) {
                int r = rm + mf * 16;
                a[mf][0] = f2tf(Ss[(r + lr    ) * SA + kc + lq]);
                a[mf][1] = f2tf(Ss[(r + lr + 8) * SA + kc + lq]);
                a[mf][2] = f2tf(Ss[(r + lr    ) * SA + kc + lq + 4]);
                a[mf][3] = f2tf(Ss[(r + lr + 8) * SA + kc + lq + 4]);
            }
            #pragma unroll
            for (int nf = 0; nf < 2; nf++) {
                int c = cn + nf * 8;
                bf[nf][0] = Vs[(kc + lq    ) * SV + c + lr];
                bf[nf][1] = Vs[(kc + lq + 4) * SV + c + lr];
            }
            #pragma unroll
            for (int mf = 0; mf < 2; mf++)
                #pragma unroll
                for (int nf = 0; nf < 2; nf++)
                    mma8(oacc[mf][nf], a[mf], bf[nf]);
        }
    }
    __syncthreads();

    // normalize and write [B,N,H,D]
    #pragma unroll
    for (int mf = 0; mf < 2; mf++) {
        int q = rm + mf * 16 + lr;
        float inv0 = 1.0f / lrow[q];
        float inv1 = 1.0f / lrow[q + 8];
        #pragma unroll
        for (int nf = 0; nf < 2; nf++) {
            int c = cn + nf * 8 + 2 * lq;
            size_t o0 = ((size_t)(b * NN + q0 + q) * HH + h) * DD + c;
            size_t o1 = ((size_t)(b * NN + q0 + q + 8) * HH + h) * DD + c;
            float2 r0 = make_float2(oacc[mf][nf][0] * inv0, oacc[mf][nf][1] * inv0);
            float2 r1 = make_float2(oacc[mf][nf][2] * inv1, oacc[mf][nf][3] * inv1);
            *(float2*)&g_attn[o0] = r0;
            *(float2*)&g_attn[o1] = r1;
        }
    }
}

extern "C" void kernel_launch(void* const* d_in, const int* in_sizes, int n_in,
                              void* d_out, int out_size)
{
    // Identify inputs by element count (all distinct).
    const float* x      = nullptr;
    const void*  pmask  = nullptr;
    const float* alibi  = nullptr;
    const float* qkv_w  = nullptr;
    const float* qkv_b  = nullptr;
    const float* proj_w = nullptr;
    const float* proj_b = nullptr;
    for (int i = 0; i < n_in; i++) {
        switch (in_sizes[i]) {
            case 6291456:   x      = (const float*)d_in[i]; break;
            case 8192:      pmask  = d_in[i];               break;
            case 201326592: alibi  = (const float*)d_in[i]; break;
            case 1769472:   qkv_w  = (const float*)d_in[i]; break;
            case 2304:      qkv_b  = (const float*)d_in[i]; break;
            case 589824:    proj_w = (const float*)d_in[i]; break;
            case 768:       proj_b = (const float*)d_in[i]; break;
        }
    }
    float* out = (float*)d_out;

    cudaFuncSetAttribute(attn_kernel,
                         cudaFuncAttributeMaxDynamicSharedMemorySize, SM_BYTES);

    mask_conv_kernel<<<1, 1024>>>(pmask);

    gemm_k<0><<<dim3(2304 / 128, 8192 / 128), 256>>>(
        x, qkv_w, qkv_b, nullptr, BB * NN, CC, 3 * CC);

    attn_kernel<<<dim3(NN / 64, HH, BB), 256, SM_BYTES>>>(alibi);

    gemm_k<1><<<dim3(768 / 128, 8192 / 128), 256>>>(
        nullptr, proj_w, proj_b, out, BB * NN, CC, CC);
}

// round 6
// speedup vs baseline: 2.1893x; 1.0098x over previous
#include <cuda_runtime.h>
#include <cuda_bf16.h>
#include <cstdint>

#define BB 4
#define NN 2048
#define HH 12
#define DD 64
#define CC 768

// ---- scratch (device globals: no allocations allowed) ----
__device__ float g_q[BB*HH*NN*DD];     // [B,H,N,D], pre-scaled by D^-0.5
__device__ float g_k[BB*HH*NN*DD];     // [B,H,N,D]
__device__ float g_v[BB*HH*NN*DD];     // [B,H,N,D]
__device__ float g_attn[BB*NN*HH*DD];  // [B,N,H,D] == [8192,768] row-major
__device__ unsigned char g_mask[BB*NN];

// ---- tf32 helpers ----
__device__ __forceinline__ uint32_t f2tf(float f) {
    uint32_t u;
    asm("cvt.rna.tf32.f32 %0, %1;" : "=r"(u) : "f"(f));
    return u;
}
__device__ __forceinline__ void mma8(float* c, const uint32_t* a, const uint32_t* b) {
    asm volatile(
        "mma.sync.aligned.m16n8k8.row.col.f32.tf32.tf32.f32 "
        "{%0,%1,%2,%3},{%4,%5,%6,%7},{%8,%9},{%0,%1,%2,%3};"
        : "+f"(c[0]), "+f"(c[1]), "+f"(c[2]), "+f"(c[3])
        : "r"(a[0]), "r"(a[1]), "r"(a[2]), "r"(a[3]), "r"(b[0]), "r"(b[1]));
}

// ============================================================
// Mask canonicalization (dtype-robust, deterministic).
// ============================================================
__global__ void mask_conv_kernel(const void* __restrict__ mraw)
{
    __shared__ int s_not_word;
    const int tid = threadIdx.x;
    if (tid == 0) s_not_word = 0;
    __syncthreads();

    const unsigned int* w = (const unsigned int*)mraw;
    for (int i = tid; i < 2048; i += blockDim.x) {
        unsigned int v = w[i];
        if (v != 0u && v != 1u && v != 0x3F800000u) atomicOr(&s_not_word, 1);
    }
    __syncthreads();

    const int wordlike = !s_not_word;
    const unsigned char* bptr = (const unsigned char*)mraw;
    for (int i = tid; i < BB * NN; i += blockDim.x) {
        unsigned char r;
        if (wordlike) r = (unsigned char)(w[i] != 0u);
        else          r = (unsigned char)(bptr[i] != 0);
        g_mask[i] = r;
    }
}

// ============================================================
// tf32 tensor-core GEMM with smem ping-pong + register prefetch.
// 128x128x16 tiles, 256 threads (8 warps), warp tile 64x32.
// MODE 0: A = x, scatter into g_q/g_k/g_v
// MODE 1: A = g_attn, write Cout
// ============================================================
#define SG 136   // smem row stride (conflict-free frag gathers)

template<int MODE>
__global__ __launch_bounds__(256) void gemm_k(
    const float* __restrict__ A, const float* __restrict__ W,
    const float* __restrict__ bias, float* __restrict__ Cout,
    int M, int K, int Nn)
{
    __shared__ uint32_t As[2][16][SG];   // [buf][k][m] tf32
    __shared__ uint32_t Bs[2][16][SG];   // [buf][k][n] tf32

    const int tid = threadIdx.x, lane = tid & 31, w = tid >> 5;
    const int wm = w >> 2, wn = w & 3;         // warp grid 2x4
    const int lr = lane >> 2, lq = lane & 3;
    const int bm = blockIdx.y * 128, bn = blockIdx.x * 128;
    const float* Ap = (MODE == 1) ? g_attn : A;

    const int m_a = tid >> 1, k_a = (tid & 1) * 8;   // A tile loader
    const int k_b = tid >> 5, n_b = (tid & 31) * 4;  // B tile loader

    float acc[4][4][4];
    #pragma unroll
    for (int i = 0; i < 4; i++)
        #pragma unroll
        for (int j = 0; j < 4; j++)
            #pragma unroll
            for (int e = 0; e < 4; e++) acc[i][j][e] = 0.f;

    float4 pa0, pa1, pb0, pb1;

    // prefetch + store tile 0 into buf 0
    {
        const float* ap = Ap + (size_t)(bm + m_a) * K + k_a;
        pa0 = *(const float4*)(ap);
        pa1 = *(const float4*)(ap + 4);
        pb0 = *(const float4*)(W + (size_t)(k_b)     * Nn + bn + n_b);
        pb1 = *(const float4*)(W + (size_t)(k_b + 8) * Nn + bn + n_b);
        As[0][k_a + 0][m_a] = f2tf(pa0.x); As[0][k_a + 1][m_a] = f2tf(pa0.y);
        As[0][k_a + 2][m_a] = f2tf(pa0.z); As[0][k_a + 3][m_a] = f2tf(pa0.w);
        As[0][k_a + 4][m_a] = f2tf(pa1.x); As[0][k_a + 5][m_a] = f2tf(pa1.y);
        As[0][k_a + 6][m_a] = f2tf(pa1.z); As[0][k_a + 7][m_a] = f2tf(pa1.w);
        *(uint4*)&Bs[0][k_b][n_b] =
            make_uint4(f2tf(pb0.x), f2tf(pb0.y), f2tf(pb0.z), f2tf(pb0.w));
        *(uint4*)&Bs[0][k_b + 8][n_b] =
            make_uint4(f2tf(pb1.x), f2tf(pb1.y), f2tf(pb1.z), f2tf(pb1.w));
    }
    __syncthreads();

    int s = 0;
    for (int k0 = 0; k0 < K; k0 += 16) {
        const bool more = (k0 + 16 < K);
        if (more) {
            const float* ap = Ap + (size_t)(bm + m_a) * K + (k0 + 16 + k_a);
            pa0 = *(const float4*)(ap);
            pa1 = *(const float4*)(ap + 4);
            pb0 = *(const float4*)(W + (size_t)(k0 + 16 + k_b)     * Nn + bn + n_b);
            pb1 = *(const float4*)(W + (size_t)(k0 + 16 + k_b + 8) * Nn + bn + n_b);
        }

        #pragma unroll
        for (int ks = 0; ks < 16; ks += 8) {
            uint32_t a[4][4], bb[4][2];
            #pragma unroll
            for (int mf = 0; mf < 4; mf++) {
                int r = wm * 64 + mf * 16;
                a[mf][0] = As[s][ks + lq    ][r + lr];
                a[mf][1] = As[s][ks + lq    ][r + lr + 8];
                a[mf][2] = As[s][ks + lq + 4][r + lr];
                a[mf][3] = As[s][ks + lq + 4][r + lr + 8];
            }
            #pragma unroll
            for (int nf = 0; nf < 4; nf++) {
                int c = wn * 32 + nf * 8;
                bb[nf][0] = Bs[s][ks + lq    ][c + lr];
                bb[nf][1] = Bs[s][ks + lq + 4][c + lr];
            }
            #pragma unroll
            for (int mf = 0; mf < 4; mf++)
                #pragma unroll
                for (int nf = 0; nf < 4; nf++)
                    mma8(acc[mf][nf], a[mf], bb[nf]);
        }

        if (more) {
            int t = s ^ 1;
            As[t][k_a + 0][m_a] = f2tf(pa0.x); As[t][k_a + 1][m_a] = f2tf(pa0.y);
            As[t][k_a + 2][m_a] = f2tf(pa0.z); As[t][k_a + 3][m_a] = f2tf(pa0.w);
            As[t][k_a + 4][m_a] = f2tf(pa1.x); As[t][k_a + 5][m_a] = f2tf(pa1.y);
            As[t][k_a + 6][m_a] = f2tf(pa1.z); As[t][k_a + 7][m_a] = f2tf(pa1.w);
            *(uint4*)&Bs[t][k_b][n_b] =
                make_uint4(f2tf(pb0.x), f2tf(pb0.y), f2tf(pb0.z), f2tf(pb0.w));
            *(uint4*)&Bs[t][k_b + 8][n_b] =
                make_uint4(f2tf(pb1.x), f2tf(pb1.y), f2tf(pb1.z), f2tf(pb1.w));
        }
        __syncthreads();
        s ^= 1;
    }

    // epilogue
    #pragma unroll
    for (int mf = 0; mf < 4; mf++) {
        #pragma unroll
        for (int nf = 0; nf < 4; nf++) {
            #pragma unroll
            for (int e = 0; e < 4; e++) {
                int rr = bm + wm * 64 + mf * 16 + lr + ((e >= 2) ? 8 : 0);
                int cc = bn + wn * 32 + nf * 8 + 2 * lq + (e & 1);
                float v = acc[mf][nf][e] + bias[cc];
                if (MODE == 0) {
                    int which = cc / CC;
                    int hc = cc - which * CC;
                    int hh = hc >> 6, d = hc & 63;
                    int b = rr >> 11, n = rr & 2047;
                    size_t off = ((size_t)((b * HH + hh) * NN + n)) * DD + d;
                    if (which == 0)      g_q[off] = v * 0.125f;
                    else if (which == 1) g_k[off] = v;
                    else                 g_v[off] = v;
                } else {
                    Cout[(size_t)rr * Nn + cc] = v;
                }
            }
        }
    }
}

// ============================================================
// Fused flash attention, tf32 tensor cores, 128q x 64k tiles.
// grid = (N/128, H, B); 256 threads (8 warps).
// Warp grid 2x4: warp tile 64q x 16k -> frags 4x2 (m16n8k8).
// ============================================================
#define SA 68   // stride Qs/Ks/Ss (68 % 32 == 4 -> frag gathers conflict-free)
#define SV 72   // stride Vs       (72 % 32 == 8 -> conflict-free)
#define ATT_SM_FLOATS (128*SA + 64*SA + 64*SV + 128*SA + 3*128 + 64)
#define ATT_SM_BYTES  (ATT_SM_FLOATS * 4)   // 107,264 B -> 2 CTAs/SM

__global__ __launch_bounds__(256, 2) void attn_kernel(
    const float* __restrict__ alibi)
{
    extern __shared__ float sm[];
    uint32_t* Qs = (uint32_t*)sm;            // [128][SA] tf32 (pre-scaled)
    uint32_t* Ks = Qs + 128 * SA;            // [64][SA]  Ks[key][d]
    uint32_t* Vs = Ks + 64 * SA;             // [64][SV]  Vs[key][d]
    float*    Ss = (float*)(Vs + 64 * SV);   // [128][SA] alibi -> scores -> probs
    float* mrow = Ss + 128 * SA;
    float* lrow = mrow + 128;
    float* frow = lrow + 128;
    float* mkf  = frow + 128;

    const int tid = threadIdx.x, lane = tid & 31, w = tid >> 5;
    const int wm = w >> 2, wn = w & 3;       // 2 x 4
    const int lr = lane >> 2, lq = lane & 3;
    const int qt = blockIdx.x, h = blockIdx.y, b = blockIdx.z;
    const int q0 = qt * 128;
    const int bh = b * HH + h;
    const int rm = wm * 64;                  // warp q-row base (64 rows)
    const int cn = wn * 16;                  // warp key/d-col base (16 cols)

    // load Q tile (128x64, convert to tf32)
    const float* Qg = g_q + ((size_t)(bh * NN + q0)) * DD;
    #pragma unroll
    for (int it = 0; it < 8; it++) {
        int e = tid * 4 + it * 1024;
        int i = e >> 6, d = e & 63;
        float4 v = *(const float4*)(Qg + i * 64 + d);
        *(uint4*)&Qs[i * SA + d] =
            make_uint4(f2tf(v.x), f2tf(v.y), f2tf(v.z), f2tf(v.w));
    }
    if (tid < 128) { mrow[tid] = -1e30f; lrow[tid] = 0.f; }

    float oacc[4][2][4];
    #pragma unroll
    for (int i = 0; i < 4; i++)
        #pragma unroll
        for (int j = 0; j < 2; j++)
            #pragma unroll
            for (int e = 0; e < 4; e++) oacc[i][j][e] = 0.f;

    const size_t abase = ((size_t)bh * NN + q0) * NN;

    for (int kt = 0; kt < 32; kt++) {
        __syncthreads();   // Q/mrow ready (kt=0) / prev PV reads of Ss,Vs done
        const int kc0 = kt * 64;
        const float* Kg = g_k + ((size_t)(bh * NN + kc0)) * DD;
        const float* Vg = g_v + ((size_t)(bh * NN + kc0)) * DD;

        #pragma unroll
        for (int it = 0; it < 4; it++) {
            int e = tid * 4 + it * 1024;
            int r0 = e >> 6, c0 = e & 63;
            float4 kv = *(const float4*)(Kg + r0 * 64 + c0);
            *(uint4*)&Ks[r0 * SA + c0] =
                make_uint4(f2tf(kv.x), f2tf(kv.y), f2tf(kv.z), f2tf(kv.w));
            float4 vv = *(const float4*)(Vg + r0 * 64 + c0);
            *(uint4*)&Vs[r0 * SV + c0] =
                make_uint4(f2tf(vv.x), f2tf(vv.y), f2tf(vv.z), f2tf(vv.w));
        }
        #pragma unroll
        for (int it = 0; it < 8; it++) {
            int e = tid * 4 + it * 1024;
            int i = e >> 6, j = e & 63;
            float4 av = *(const float4*)(alibi + abase + (size_t)i * NN + kc0 + j);
            *(float4*)&Ss[i * SA + j] = av;
        }
        if (tid < 64) mkf[tid] = g_mask[b * NN + kc0 + tid] ? 1.f : 0.f;
        __syncthreads();

        // ---- S = Q @ K^T ----
        float sacc[4][2][4];
        #pragma unroll
        for (int i = 0; i < 4; i++)
            #pragma unroll
            for (int j = 0; j < 2; j++)
                #pragma unroll
                for (int e = 0; e < 4; e++) sacc[i][j][e] = 0.f;

        #pragma unroll
        for (int kc = 0; kc < 64; kc += 8) {
            uint32_t a[4][4], bf[2][2];
            #pragma unroll
            for (int mf = 0; mf < 4; mf++) {
                int r = rm + mf * 16;
                a[mf][0] = Qs[(r + lr    ) * SA + kc + lq];
                a[mf][1] = Qs[(r + lr + 8) * SA + kc + lq];
                a[mf][2] = Qs[(r + lr    ) * SA + kc + lq + 4];
                a[mf][3] = Qs[(r + lr + 8) * SA + kc + lq + 4];
            }
            #pragma unroll
            for (int nf = 0; nf < 2; nf++) {
                int c = cn + nf * 8;
                bf[nf][0] = Ks[(c + lr) * SA + kc + lq];
                bf[nf][1] = Ks[(c + lr) * SA + kc + lq + 4];
            }
            #pragma unroll
            for (int mf = 0; mf < 4; mf++)
                #pragma unroll
                for (int nf = 0; nf < 2; nf++)
                    mma8(sacc[mf][nf], a[mf], bf[nf]);
        }

        // ---- + alibi (in Ss), mask, write scores back to Ss ----
        #pragma unroll
        for (int mf = 0; mf < 4; mf++) {
            int q = rm + mf * 16 + lr;
            #pragma unroll
            for (int nf = 0; nf < 2; nf++) {
                int c = cn + nf * 8 + 2 * lq;
                float m0 = mkf[c], m1 = mkf[c + 1];
                int i0 = q * SA + c, i1 = (q + 8) * SA + c;
                float v0 = sacc[mf][nf][0] + Ss[i0];
                float v1 = sacc[mf][nf][1] + Ss[i0 + 1];
                float v2 = sacc[mf][nf][2] + Ss[i1];
                float v3 = sacc[mf][nf][3] + Ss[i1 + 1];
                Ss[i0]     = (m0 != 0.f) ? -1e30f : v0;
                Ss[i0 + 1] = (m1 != 0.f) ? -1e30f : v1;
                Ss[i1]     = (m0 != 0.f) ? -1e30f : v2;
                Ss[i1 + 1] = (m1 != 0.f) ? -1e30f : v3;
            }
        }
        __syncthreads();

        // ---- online softmax: 2 lanes per row, 32 cols each ----
        {
            int r = tid >> 1;
            int sb = r * SA + (tid & 1) * 32;
            float mt = -1e30f;
            #pragma unroll
            for (int jj = 0; jj < 32; jj++) mt = fmaxf(mt, Ss[sb + jj]);
            mt = fmaxf(mt, __shfl_xor_sync(0xffffffffu, mt, 1));
            float mold = mrow[r];
            float mnew = fmaxf(mold, mt);
            float fac = __expf(mold - mnew);
            float ssum = 0.f;
            #pragma unroll
            for (int jj = 0; jj < 32; jj++) {
                float p = __expf(Ss[sb + jj] - mnew);
                Ss[sb + jj] = p;
                ssum += p;
            }
            ssum += __shfl_xor_sync(0xffffffffu, ssum, 1);
            if ((tid & 1) == 0) {
                lrow[r] = lrow[r] * fac + ssum;
                mrow[r] = mnew;
                frow[r] = fac;
            }
        }
        __syncthreads();

        // ---- rescale O, then O += P @ V ----
        #pragma unroll
        for (int mf = 0; mf < 4; mf++) {
            float f0 = frow[rm + mf * 16 + lr];
            float f1 = frow[rm + mf * 16 + lr + 8];
            #pragma unroll
            for (int nf = 0; nf < 2; nf++) {
                oacc[mf][nf][0] *= f0; oacc[mf][nf][1] *= f0;
                oacc[mf][nf][2] *= f1; oacc[mf][nf][3] *= f1;
            }
        }
        #pragma unroll
        for (int kc = 0; kc < 64; kc += 8) {
            uint32_t a[4][4], bf[2][2];
            #pragma unroll
            for (int mf = 0; mf < 4; mf++) {
                int r = rm + mf * 16;
                a[mf][0] = f2tf(Ss[(r + lr    ) * SA + kc + lq]);
                a[mf][1] = f2tf(Ss[(r + lr + 8) * SA + kc + lq]);
                a[mf][2] = f2tf(Ss[(r + lr    ) * SA + kc + lq + 4]);
                a[mf][3] = f2tf(Ss[(r + lr + 8) * SA + kc + lq + 4]);
            }
            #pragma unroll
            for (int nf = 0; nf < 2; nf++) {
                int c = cn + nf * 8;
                bf[nf][0] = Vs[(kc + lq    ) * SV + c + lr];
                bf[nf][1] = Vs[(kc + lq + 4) * SV + c + lr];
            }
            #pragma unroll
            for (int mf = 0; mf < 4; mf++)
                #pragma unroll
                for (int nf = 0; nf < 2; nf++)
                    mma8(oacc[mf][nf], a[mf], bf[nf]);
        }
    }

    // normalize and write [B,N,H,D]
    #pragma unroll
    for (int mf = 0; mf < 4; mf++) {
        int q = rm + mf * 16 + lr;
        float inv0 = 1.0f / lrow[q];
        float inv1 = 1.0f / lrow[q + 8];
        #pragma unroll
        for (int nf = 0; nf < 2; nf++) {
            int c = cn + nf * 8 + 2 * lq;
            size_t o0 = ((size_t)(b * NN + q0 + q) * HH + h) * DD + c;
            size_t o1 = ((size_t)(b * NN + q0 + q + 8) * HH + h) * DD + c;
            *(float2*)&g_attn[o0] =
                make_float2(oacc[mf][nf][0] * inv0, oacc[mf][nf][1] * inv0);
            *(float2*)&g_attn[o1] =
                make_float2(oacc[mf][nf][2] * inv1, oacc[mf][nf][3] * inv1);
        }
    }
}

extern "C" void kernel_launch(void* const* d_in, const int* in_sizes, int n_in,
                              void* d_out, int out_size)
{
    // Identify inputs by element count (all distinct).
    const float* x      = nullptr;
    const void*  pmask  = nullptr;
    const float* alibi  = nullptr;
    const float* qkv_w  = nullptr;
    const float* qkv_b  = nullptr;
    const float* proj_w = nullptr;
    const float* proj_b = nullptr;
    for (int i = 0; i < n_in; i++) {
        switch (in_sizes[i]) {
            case 6291456:   x      = (const float*)d_in[i]; break;
            case 8192:      pmask  = d_in[i];               break;
            case 201326592: alibi  = (const float*)d_in[i]; break;
            case 1769472:   qkv_w  = (const float*)d_in[i]; break;
            case 2304:      qkv_b  = (const float*)d_in[i]; break;
            case 589824:    proj_w = (const float*)d_in[i]; break;
            case 768:       proj_b = (const float*)d_in[i]; break;
        }
    }
    float* out = (float*)d_out;

    cudaFuncSetAttribute(attn_kernel,
                         cudaFuncAttributeMaxDynamicSharedMemorySize, ATT_SM_BYTES);

    mask_conv_kernel<<<1, 1024>>>(pmask);

    gemm_k<0><<<dim3(2304 / 128, 8192 / 128), 256>>>(
        x, qkv_w, qkv_b, nullptr, BB * NN, CC, 3 * CC);

    attn_kernel<<<dim3(NN / 128, HH, BB), 256, ATT_SM_BYTES>>>(alibi);

    gemm_k<1><<<dim3(768 / 128, 8192 / 128), 256>>>(
        nullptr, proj_w, proj_b, out, BB * NN, CC, CC);
}

// round 7
// speedup vs baseline: 2.4215x; 1.1060x over previous
#include <cuda_runtime.h>
#include <cuda_bf16.h>
#include <cstdint>

#define BB 4
#define NN 2048
#define HH 12
#define DD 64
#define CC 768
#define QKVW 2304

// ---- scratch (device globals: no allocations allowed) ----
__device__ float g_qkv[(size_t)BB*NN*QKVW];   // [B*N, 3*C]: q|k|v blocks, row-major
__device__ float g_attn[(size_t)BB*NN*HH*DD]; // [B,N,H,D] == [8192,768] row-major
__device__ unsigned char g_mask[BB*NN];

// ---- tf32 helpers ----
__device__ __forceinline__ uint32_t f2tf(float f) {
    uint32_t u;
    asm("cvt.rna.tf32.f32 %0, %1;" : "=r"(u) : "f"(f));
    return u;
}
__device__ __forceinline__ void mma8(float* c, const uint32_t* a, const uint32_t* b) {
    asm volatile(
        "mma.sync.aligned.m16n8k8.row.col.f32.tf32.tf32.f32 "
        "{%0,%1,%2,%3},{%4,%5,%6,%7},{%8,%9},{%0,%1,%2,%3};"
        : "+f"(c[0]), "+f"(c[1]), "+f"(c[2]), "+f"(c[3])
        : "r"(a[0]), "r"(a[1]), "r"(a[2]), "r"(a[3]), "r"(b[0]), "r"(b[1]));
}
// ---- cp.async helpers ----
__device__ __forceinline__ void cpa16(void* smem, const void* g) {
    uint32_t s = (uint32_t)__cvta_generic_to_shared(smem);
    asm volatile("cp.async.cg.shared.global [%0], [%1], 16;" :: "r"(s), "l"(g));
}
#define CP_COMMIT() asm volatile("cp.async.commit_group;")
#define CP_WAIT(n)  asm volatile("cp.async.wait_group %0;" :: "n"(n))

// ============================================================
// Mask canonicalization (dtype-robust, deterministic).
// ============================================================
__global__ void mask_conv_kernel(const void* __restrict__ mraw)
{
    __shared__ int s_not_word;
    const int tid = threadIdx.x;
    if (tid == 0) s_not_word = 0;
    __syncthreads();

    const unsigned int* w = (const unsigned int*)mraw;
    for (int i = tid; i < 2048; i += blockDim.x) {
        unsigned int v = w[i];
        if (v != 0u && v != 1u && v != 0x3F800000u) atomicOr(&s_not_word, 1);
    }
    __syncthreads();

    const int wordlike = !s_not_word;
    const unsigned char* bptr = (const unsigned char*)mraw;
    for (int i = tid; i < BB * NN; i += blockDim.x) {
        unsigned char r;
        if (wordlike) r = (unsigned char)(w[i] != 0u);
        else          r = (unsigned char)(bptr[i] != 0);
        g_mask[i] = r;
    }
}

// ============================================================
// tf32 tensor-core GEMM (round-5 structure: single smem buffer,
// register prefetch). 128x128x16 tiles, 256 threads, warp 64x32.
// MODE 0: A = x,      C -> g_qkv   (plain row-major, coalesced)
// MODE 1: A = g_attn, C -> Cout
// ============================================================
#define SG 136

template<int MODE>
__global__ __launch_bounds__(256) void gemm_k(
    const float* __restrict__ A, const float* __restrict__ W,
    const float* __restrict__ bias, float* __restrict__ Cout,
    int M, int K, int Nn)
{
    __shared__ uint32_t As[16][SG];
    __shared__ uint32_t Bs[16][SG];

    const int tid = threadIdx.x, lane = tid & 31, w = tid >> 5;
    const int wm = w >> 2, wn = w & 3;
    const int lr = lane >> 2, lq = lane & 3;
    const int bm = blockIdx.y * 128, bn = blockIdx.x * 128;
    const float* Ap = (MODE == 1) ? g_attn : A;
    float* Cp = (MODE == 0) ? g_qkv : Cout;

    const int m_a = tid >> 1, k_a = (tid & 1) * 8;
    const int k_b = tid >> 5, n_b = (tid & 31) * 4;

    float acc[4][4][4];
    #pragma unroll
    for (int i = 0; i < 4; i++)
        #pragma unroll
        for (int j = 0; j < 4; j++)
            #pragma unroll
            for (int e = 0; e < 4; e++) acc[i][j][e] = 0.f;

    float4 pa0, pa1, pb0, pb1;
    {
        const float* ap = Ap + (size_t)(bm + m_a) * K + k_a;
        pa0 = *(const float4*)(ap);
        pa1 = *(const float4*)(ap + 4);
        pb0 = *(const float4*)(W + (size_t)(k_b)     * Nn + bn + n_b);
        pb1 = *(const float4*)(W + (size_t)(k_b + 8) * Nn + bn + n_b);
    }
    {
        As[k_a + 0][m_a] = f2tf(pa0.x); As[k_a + 1][m_a] = f2tf(pa0.y);
        As[k_a + 2][m_a] = f2tf(pa0.z); As[k_a + 3][m_a] = f2tf(pa0.w);
        As[k_a + 4][m_a] = f2tf(pa1.x); As[k_a + 5][m_a] = f2tf(pa1.y);
        As[k_a + 6][m_a] = f2tf(pa1.z); As[k_a + 7][m_a] = f2tf(pa1.w);
        *(uint4*)&Bs[k_b][n_b] =
            make_uint4(f2tf(pb0.x), f2tf(pb0.y), f2tf(pb0.z), f2tf(pb0.w));
        *(uint4*)&Bs[k_b + 8][n_b] =
            make_uint4(f2tf(pb1.x), f2tf(pb1.y), f2tf(pb1.z), f2tf(pb1.w));
    }
    __syncthreads();

    for (int k0 = 0; k0 < K; k0 += 16) {
        const bool more = (k0 + 16 < K);
        if (more) {
            const float* ap = Ap + (size_t)(bm + m_a) * K + (k0 + 16 + k_a);
            pa0 = *(const float4*)(ap);
            pa1 = *(const float4*)(ap + 4);
            pb0 = *(const float4*)(W + (size_t)(k0 + 16 + k_b)     * Nn + bn + n_b);
            pb1 = *(const float4*)(W + (size_t)(k0 + 16 + k_b + 8) * Nn + bn + n_b);
        }

        #pragma unroll
        for (int ks = 0; ks < 16; ks += 8) {
            uint32_t a[4][4], bb[4][2];
            #pragma unroll
            for (int mf = 0; mf < 4; mf++) {
                int r = wm * 64 + mf * 16;
                a[mf][0] = As[ks + lq    ][r + lr];
                a[mf][1] = As[ks + lq    ][r + lr + 8];
                a[mf][2] = As[ks + lq + 4][r + lr];
                a[mf][3] = As[ks + lq + 4][r + lr + 8];
            }
            #pragma unroll
            for (int nf = 0; nf < 4; nf++) {
                int c = wn * 32 + nf * 8;
                bb[nf][0] = Bs[ks + lq    ][c + lr];
                bb[nf][1] = Bs[ks + lq + 4][c + lr];
            }
            #pragma unroll
            for (int mf = 0; mf < 4; mf++)
                #pragma unroll
                for (int nf = 0; nf < 4; nf++)
                    mma8(acc[mf][nf], a[mf], bb[nf]);
        }
        __syncthreads();

        if (more) {
            As[k_a + 0][m_a] = f2tf(pa0.x); As[k_a + 1][m_a] = f2tf(pa0.y);
            As[k_a + 2][m_a] = f2tf(pa0.z); As[k_a + 3][m_a] = f2tf(pa0.w);
            As[k_a + 4][m_a] = f2tf(pa1.x); As[k_a + 5][m_a] = f2tf(pa1.y);
            As[k_a + 6][m_a] = f2tf(pa1.z); As[k_a + 7][m_a] = f2tf(pa1.w);
            *(uint4*)&Bs[k_b][n_b] =
                make_uint4(f2tf(pb0.x), f2tf(pb0.y), f2tf(pb0.z), f2tf(pb0.w));
            *(uint4*)&Bs[k_b + 8][n_b] =
                make_uint4(f2tf(pb1.x), f2tf(pb1.y), f2tf(pb1.z), f2tf(pb1.w));
            __syncthreads();
        }
    }

    // coalesced float2 epilogue
    #pragma unroll
    for (int mf = 0; mf < 4; mf++) {
        int rr0 = bm + wm * 64 + mf * 16 + lr;
        #pragma unroll
        for (int nf = 0; nf < 4; nf++) {
            int cc = bn + wn * 32 + nf * 8 + 2 * lq;
            float bx = bias[cc], by = bias[cc + 1];
            *(float2*)&Cp[(size_t)rr0 * Nn + cc] =
                make_float2(acc[mf][nf][0] + bx, acc[mf][nf][1] + by);
            *(float2*)&Cp[(size_t)(rr0 + 8) * Nn + cc] =
                make_float2(acc[mf][nf][2] + bx, acc[mf][nf][3] + by);
        }
    }
}

// ============================================================
// Fused flash attention, tf32 MMA, cp.async pipelined.
// grid = (N/64, H, B); 256 threads (8 warps); 64 q-rows per CTA.
// Warp grid 2x4: warp tile 32q x 16k, frags 2x2 (m16n8k8).
// K: double-buffered cp.async, prefetched 1 tile ahead.
// V: single-buffer cp.async, deferred wait (hidden under QK^T).
// Alibi: straight to registers (fragment layout), no smem.
// ============================================================
#define SK 68   // Q/K stride (floats): 4*lr+lq distinct -> conflict-free
#define SV 72   // V stride: 8*lq+lr distinct -> conflict-free
#define SS 68
#define ATT_SM_FLOATS (64*SK + 2*64*SK + 64*SV + 64*SS + 3*64)
#define ATT_SM_BYTES  (ATT_SM_FLOATS * 4)   // 88,832 B -> 2 CTAs/SM

__global__ __launch_bounds__(256, 2) void attn_kernel(
    const float* __restrict__ alibi)
{
    extern __shared__ float sm[];
    uint32_t* Qs = (uint32_t*)sm;           // [64][SK] tf32, pre-scaled
    float* Kf   = sm + 64 * SK;             // [2][64][SK] raw fp32
    float* Vf   = Kf + 2 * 64 * SK;         // [64][SV]    raw fp32
    float* Ss   = Vf + 64 * SV;             // [64][SS] scores -> tf32 probs
    float* mrow = Ss + 64 * SS;
    float* lrow = mrow + 64;
    float* frow = lrow + 64;

    const int tid = threadIdx.x, lane = tid & 31, w = tid >> 5;
    const int wm = w >> 2, wn = w & 3;      // 2 x 4
    const int lr = lane >> 2, lq = lane & 3;
    const int qt = blockIdx.x, h = blockIdx.y, b = blockIdx.z;
    const int q0 = qt * 64;
    const int rm = wm * 32, cn = wn * 16;

    const int ldrow = tid >> 4;             // 0..15 (chunk row group)
    const int ldcol = (tid & 15) * 4;       // 0..60

    const float* Qg = g_qkv + (size_t)(b * NN + q0) * QKVW + h * 64;
    const float* Kbase = g_qkv + (size_t)(b * NN) * QKVW + CC + h * 64;
    const float* Vbase = g_qkv + (size_t)(b * NN) * QKVW + 2 * CC + h * 64;

    // ---- load Q (scale + tf32) ----
    #pragma unroll
    for (int it = 0; it < 4; it++) {
        int row = ldrow + it * 16;
        float4 v = *(const float4*)(Qg + (size_t)row * QKVW + ldcol);
        *(uint4*)&Qs[row * SK + ldcol] =
            make_uint4(f2tf(v.x * 0.125f), f2tf(v.y * 0.125f),
                       f2tf(v.z * 0.125f), f2tf(v.w * 0.125f));
    }
    if (tid < 64) { mrow[tid] = -1e30f; lrow[tid] = 0.f; }

    // ---- prefetch K(0) ----
    #pragma unroll
    for (int it = 0; it < 4; it++) {
        int row = ldrow + it * 16;
        cpa16(&Kf[row * SK + ldcol], Kbase + (size_t)row * QKVW + ldcol);
    }
    CP_COMMIT();

    float oacc[2][2][4];
    #pragma unroll
    for (int i = 0; i < 2; i++)
        #pragma unroll
        for (int j = 0; j < 2; j++)
            #pragma unroll
            for (int e = 0; e < 4; e++) oacc[i][j][e] = 0.f;

    const size_t abase = ((size_t)(b * HH + h) * NN + q0) * NN;

    for (int kt = 0; kt < 32; kt++) {
        const int kc0 = kt * 64;
        __syncthreads();   // (a) prev PV done; Q/init visible at kt=0

        // issue V(kt) cp.async (waited later, hidden under QK^T)
        #pragma unroll
        for (int it = 0; it < 4; it++) {
            int row = ldrow + it * 16;
            cpa16(&Vf[row * SV + ldcol],
                  Vbase + (size_t)(kc0 + row) * QKVW + ldcol);
        }
        CP_COMMIT();

        // alibi + mask straight to registers (consumed after QK^T)
        float2 al[2][2][2];
        unsigned short mk[2];
        #pragma unroll
        for (int mf = 0; mf < 2; mf++) {
            int q = rm + mf * 16 + lr;
            #pragma unroll
            for (int nf = 0; nf < 2; nf++) {
                int c = cn + nf * 8 + 2 * lq;
                al[mf][nf][0] = *(const float2*)(alibi + abase + (size_t)q * NN + kc0 + c);
                al[mf][nf][1] = *(const float2*)(alibi + abase + (size_t)(q + 8) * NN + kc0 + c);
            }
        }
        #pragma unroll
        for (int nf = 0; nf < 2; nf++)
            mk[nf] = *(const unsigned short*)&g_mask[b * NN + kc0 + cn + nf * 8 + 2 * lq];

        CP_WAIT(1);        // K(kt) landed (V still in flight)
        __syncthreads();   // (b) K visible to all

        // ---- S = Q @ K^T ----
        const float* Kb = Kf + (kt & 1) * 64 * SK;
        float sacc[2][2][4];
        #pragma unroll
        for (int i = 0; i < 2; i++)
            #pragma unroll
            for (int j = 0; j < 2; j++)
                #pragma unroll
                for (int e = 0; e < 4; e++) sacc[i][j][e] = 0.f;

        #pragma unroll
        for (int kc = 0; kc < 64; kc += 8) {
            uint32_t a[2][4], bf[2][2];
            #pragma unroll
            for (int mf = 0; mf < 2; mf++) {
                int r = rm + mf * 16;
                a[mf][0] = Qs[(r + lr    ) * SK + kc + lq];
                a[mf][1] = Qs[(r + lr + 8) * SK + kc + lq];
                a[mf][2] = Qs[(r + lr    ) * SK + kc + lq + 4];
                a[mf][3] = Qs[(r + lr + 8) * SK + kc + lq + 4];
            }
            #pragma unroll
            for (int nf = 0; nf < 2; nf++) {
                int c = cn + nf * 8;
                bf[nf][0] = f2tf(Kb[(c + lr) * SK + kc + lq]);
                bf[nf][1] = f2tf(Kb[(c + lr) * SK + kc + lq + 4]);
            }
            #pragma unroll
            for (int mf = 0; mf < 2; mf++)
                #pragma unroll
                for (int nf = 0; nf < 2; nf++)
                    mma8(sacc[mf][nf], a[mf], bf[nf]);
        }

        // prefetch K(kt+1) into other buffer; then wait V
        if (kt < 31) {
            float* Kn = Kf + ((kt + 1) & 1) * 64 * SK;
            #pragma unroll
            for (int it = 0; it < 4; it++) {
                int row = ldrow + it * 16;
                cpa16(&Kn[row * SK + ldcol],
                      Kbase + (size_t)(kc0 + 64 + row) * QKVW + ldcol);
            }
            CP_COMMIT();
            CP_WAIT(1);    // V(kt) landed (K(kt+1) in flight)
        } else {
            CP_WAIT(0);    // V(31) landed
        }

        // ---- + alibi, mask -> Ss ----
        #pragma unroll
        for (int mf = 0; mf < 2; mf++) {
            int q = rm + mf * 16 + lr;
            #pragma unroll
            for (int nf = 0; nf < 2; nf++) {
                int c = cn + nf * 8 + 2 * lq;
                float m0 = (mk[nf] & 0xFF)  ? 1.f : 0.f;
                float m1 = (mk[nf] >> 8)    ? 1.f : 0.f;
                float v0 = sacc[mf][nf][0] + al[mf][nf][0].x;
                float v1 = sacc[mf][nf][1] + al[mf][nf][0].y;
                float v2 = sacc[mf][nf][2] + al[mf][nf][1].x;
                float v3 = sacc[mf][nf][3] + al[mf][nf][1].y;
                *(float2*)&Ss[q * SS + c] =
                    make_float2(m0 != 0.f ? -1e30f : v0, m1 != 0.f ? -1e30f : v1);
                *(float2*)&Ss[(q + 8) * SS + c] =
                    make_float2(m0 != 0.f ? -1e30f : v2, m1 != 0.f ? -1e30f : v3);
            }
        }
        __syncthreads();   // (c) scores + V visible

        // ---- online softmax: 4 lanes/row, 16 cols each; store tf32 probs ----
        {
            int r = tid >> 2, qq = tid & 3;
            int sb = r * SS + qq * 16;
            float mt = -1e30f;
            #pragma unroll
            for (int jj = 0; jj < 16; jj++) mt = fmaxf(mt, Ss[sb + jj]);
            mt = fmaxf(mt, __shfl_xor_sync(0xffffffffu, mt, 1));
            mt = fmaxf(mt, __shfl_xor_sync(0xffffffffu, mt, 2));
            float mold = mrow[r];
            float mnew = fmaxf(mold, mt);
            float fac = __expf(mold - mnew);
            float ssum = 0.f;
            #pragma unroll
            for (int jj = 0; jj < 16; jj++) {
                float p = __expf(Ss[sb + jj] - mnew);
                ssum += p;
                Ss[sb + jj] = __uint_as_float(f2tf(p));
            }
            ssum += __shfl_xor_sync(0xffffffffu, ssum, 1);
            ssum += __shfl_xor_sync(0xffffffffu, ssum, 2);
            if (qq == 0) {
                lrow[r] = lrow[r] * fac + ssum;
                mrow[r] = mnew;
                frow[r] = fac;
            }
        }
        __syncthreads();   // (d)

        // ---- rescale O, then O += P @ V ----
        #pragma unroll
        for (int mf = 0; mf < 2; mf++) {
            float f0 = frow[rm + mf * 16 + lr];
            float f1 = frow[rm + mf * 16 + lr + 8];
            #pragma unroll
            for (int nf = 0; nf < 2; nf++) {
                oacc[mf][nf][0] *= f0; oacc[mf][nf][1] *= f0;
                oacc[mf][nf][2] *= f1; oacc[mf][nf][3] *= f1;
            }
        }
        #pragma unroll
        for (int kc = 0; kc < 64; kc += 8) {
            uint32_t a[2][4], bf[2][2];
            #pragma unroll
            for (int mf = 0; mf < 2; mf++) {
                int r = rm + mf * 16;
                a[mf][0] = __float_as_uint(Ss[(r + lr    ) * SS + kc + lq]);
                a[mf][1] = __float_as_uint(Ss[(r + lr + 8) * SS + kc + lq]);
                a[mf][2] = __float_as_uint(Ss[(r + lr    ) * SS + kc + lq + 4]);
                a[mf][3] = __float_as_uint(Ss[(r + lr + 8) * SS + kc + lq + 4]);
            }
            #pragma unroll
            for (int nf = 0; nf < 2; nf++) {
                int c = cn + nf * 8;
                bf[nf][0] = f2tf(Vf[(kc + lq    ) * SV + c + lr]);
                bf[nf][1] = f2tf(Vf[(kc + lq + 4) * SV + c + lr]);
            }
            #pragma unroll
            for (int mf = 0; mf < 2; mf++)
                #pragma unroll
                for (int nf = 0; nf < 2; nf++)
                    mma8(oacc[mf][nf], a[mf], bf[nf]);
        }
    }

    // ---- normalize and write [B,N,H,D] ----
    #pragma unroll
    for (int mf = 0; mf < 2; mf++) {
        int q = rm + mf * 16 + lr;
        float inv0 = 1.0f / lrow[q];
        float inv1 = 1.0f / lrow[q + 8];
        #pragma unroll
        for (int nf = 0; nf < 2; nf++) {
            int c = cn + nf * 8 + 2 * lq;
            size_t o0 = ((size_t)(b * NN + q0 + q) * HH + h) * DD + c;
            size_t o1 = ((size_t)(b * NN + q0 + q + 8) * HH + h) * DD + c;
            *(float2*)&g_attn[o0] =
                make_float2(oacc[mf][nf][0] * inv0, oacc[mf][nf][1] * inv0);
            *(float2*)&g_attn[o1] =
                make_float2(oacc[mf][nf][2] * inv1, oacc[mf][nf][3] * inv1);
        }
    }
}

extern "C" void kernel_launch(void* const* d_in, const int* in_sizes, int n_in,
                              void* d_out, int out_size)
{
    // Identify inputs by element count (all distinct).
    const float* x      = nullptr;
    const void*  pmask  = nullptr;
    const float* alibi  = nullptr;
    const float* qkv_w  = nullptr;
    const float* qkv_b  = nullptr;
    const float* proj_w = nullptr;
    const float* proj_b = nullptr;
    for (int i = 0; i < n_in; i++) {
        switch (in_sizes[i]) {
            case 6291456:   x      = (const float*)d_in[i]; break;
            case 8192:      pmask  = d_in[i];               break;
            case 201326592: alibi  = (const float*)d_in[i]; break;
            case 1769472:   qkv_w  = (const float*)d_in[i]; break;
            case 2304:      qkv_b  = (const float*)d_in[i]; break;
            case 589824:    proj_w = (const float*)d_in[i]; break;
            case 768:       proj_b = (const float*)d_in[i]; break;
        }
    }
    float* out = (float*)d_out;

    cudaFuncSetAttribute(attn_kernel,
                         cudaFuncAttributeMaxDynamicSharedMemorySize, ATT_SM_BYTES);

    mask_conv_kernel<<<1, 1024>>>(pmask);

    // 1) QKV projection -> g_qkv [8192, 2304] (coalesced)
    gemm_k<0><<<dim3(QKVW / 128, (BB * NN) / 128), 256>>>(
        x, qkv_w, qkv_b, nullptr, BB * NN, CC, QKVW);

    // 2) fused attention
    attn_kernel<<<dim3(NN / 64, HH, BB), 256, ATT_SM_BYTES>>>(alibi);

    // 3) output projection
    gemm_k<1><<<dim3(CC / 128, (BB * NN) / 128), 256>>>(
        nullptr, proj_w, proj_b, out, BB * NN, CC, CC);
}

// round 15
// speedup vs baseline: 2.4219x; 1.0002x over previous
#include <cuda_runtime.h>
#include <cstdint>

#define BB 4
#define NN 2048
#define HH 12
#define DD 64
#define CC 768
#define QKVW 2304

// ---- scratch (device globals: no allocations allowed) ----
__device__ float g_qkv[(size_t)BB*NN*QKVW];   // [B*N, 3*C] raw f32
__device__ float g_attn[(size_t)BB*NN*HH*DD]; // [B,N,H,D], tf32-rounded bits
__device__ float g_wT[(size_t)QKVW*CC];       // W^T [N][K], tf32-rounded bits
__device__ float g_xtf[(size_t)BB*NN*CC];     // x, tf32-rounded bits
__device__ unsigned char g_mask[BB*NN];

// ---- helpers ----
__device__ __forceinline__ uint32_t f2tf(float f) {
    uint32_t u;
    asm("cvt.rna.tf32.f32 %0, %1;" : "=r"(u) : "f"(f));
    return u;
}
__device__ __forceinline__ void mma8(float* c, const uint32_t* a, const uint32_t* b) {
    asm volatile(
        "mma.sync.aligned.m16n8k8.row.col.f32.tf32.tf32.f32 "
        "{%0,%1,%2,%3},{%4,%5,%6,%7},{%8,%9},{%0,%1,%2,%3};"
        : "+f"(c[0]), "+f"(c[1]), "+f"(c[2]), "+f"(c[3])
        : "r"(a[0]), "r"(a[1]), "r"(a[2]), "r"(a[3]), "r"(b[0]), "r"(b[1]));
}
__device__ __forceinline__ void cpa16(void* smem, const void* g) {
    uint32_t s = (uint32_t)__cvta_generic_to_shared(smem);
    asm volatile("cp.async.cg.shared.global [%0], [%1], 16;" :: "r"(s), "l"(g));
}
#define CP_COMMIT() asm volatile("cp.async.commit_group;")
#define CP_WAIT(n)  asm volatile("cp.async.wait_group %0;" :: "n"(n))

// ============================================================
// Mask canonicalization (dtype-robust, deterministic).
// ============================================================
__global__ void mask_conv_kernel(const void* __restrict__ mraw)
{
    __shared__ int s_not_word;
    const int tid = threadIdx.x;
    if (tid == 0) s_not_word = 0;
    __syncthreads();

    const unsigned int* w = (const unsigned int*)mraw;
    for (int i = tid; i < 2048; i += blockDim.x) {
        unsigned int v = w[i];
        if (v != 0u && v != 1u && v != 0x3F800000u) atomicOr(&s_not_word, 1);
    }
    __syncthreads();

    const int wordlike = !s_not_word;
    const unsigned char* bptr = (const unsigned char*)mraw;
    for (int i = tid; i < BB * NN; i += blockDim.x) {
        unsigned char r;
        if (wordlike) r = (unsigned char)(w[i] != 0u);
        else          r = (unsigned char)(bptr[i] != 0);
        g_mask[i] = r;
    }
}

// ============================================================
// x -> tf32-rounded copy (one float4 per thread)
// ============================================================
__global__ void conv_x_kernel(const float* __restrict__ x)
{
    size_t i = ((size_t)blockIdx.x * 256 + threadIdx.x) * 4;
    float4 v = *(const float4*)(x + i);
    *(uint4*)&g_xtf[i] = make_uint4(f2tf(v.x), f2tf(v.y), f2tf(v.z), f2tf(v.w));
}

// ============================================================
// Tiled transpose with tf32 rounding: g_wT[c][r] = tf32(in[r][c])
// ============================================================
__global__ void transpose_k(const float* __restrict__ in, int R, int C)
{
    __shared__ float t[32][33];
    int c0 = blockIdx.x * 32, r0 = blockIdx.y * 32;
    int x = threadIdx.x, y = threadIdx.y;    // 32 x 8
    #pragma unroll
    for (int i = 0; i < 32; i += 8)
        t[y + i][x] = in[(size_t)(r0 + y + i) * C + c0 + x];
    __syncthreads();
    #pragma unroll
    for (int i = 0; i < 32; i += 8)
        g_wT[(size_t)(c0 + y + i) * R + r0 + x] = __uint_as_float(f2tf(t[x][y + i]));
}

// ============================================================
// tf32 GEMM, 3-stage cp.async pipeline, 1 barrier per 16-k chunk.
// Inputs pre-rounded tf32 bits (device globals only — no host-
// passed device symbols!). 128x128 tiles, 256 threads.
// MODE 0: A = g_xtf,  C -> g_qkv (+bias)
// MODE 1: A = g_attn, C -> Cout  (+bias)
// ============================================================
#define SP 20                                  // smem row stride (floats)
#define GCH 16                                 // k per chunk
#define G_STAGE (128 * SP * 2)                 // A + B floats per stage
#define GEMM_SM_BYTES (3 * G_STAGE * 4)        // 61,440

template<int MODE>
__global__ __launch_bounds__(256) void gemm_tc(
    const float* __restrict__ bias, float* __restrict__ Cout, int K, int Nn)
{
    extern __shared__ float gs[];
    const int tid = threadIdx.x, lane = tid & 31, w = tid >> 5;
    const int wm = w >> 2, wn = w & 3;
    const int lr = lane >> 2, lq = lane & 3;
    const int bm = blockIdx.y * 128, bn = blockIdx.x * 128;
    const float* Ap = (MODE == 1) ? g_attn : g_xtf;   // device-side symbol access
    float* Cp = (MODE == 0) ? g_qkv : Cout;
    const int nch = K / GCH;

    const int row = tid >> 1, kq = (tid & 1) * 8;

    float acc[4][4][4];
    #pragma unroll
    for (int i = 0; i < 4; i++)
        #pragma unroll
        for (int j = 0; j < 4; j++)
            #pragma unroll
            for (int e = 0; e < 4; e++) acc[i][j][e] = 0.f;

    #define G_ISSUE(c) do { \
        float* st = gs + ((c) % 3) * G_STAGE; \
        const float* ga = Ap + (size_t)(bm + row) * K + (c) * GCH + kq; \
        cpa16(st + row * SP + kq, ga); \
        cpa16(st + row * SP + kq + 4, ga + 4); \
        const float* gb = g_wT + (size_t)(bn + row) * K + (c) * GCH + kq; \
        cpa16(st + 128 * SP + row * SP + kq, gb); \
        cpa16(st + 128 * SP + row * SP + kq + 4, gb + 4); \
        CP_COMMIT(); \
    } while (0)

    G_ISSUE(0);
    G_ISSUE(1);

    for (int c = 0; c < nch; c++) {
        if (c + 1 < nch) { CP_WAIT(1); } else { CP_WAIT(0); }
        __syncthreads();
        const uint32_t* As = (const uint32_t*)(gs + (c % 3) * G_STAGE);
        const uint32_t* Bs = As + 128 * SP;
        #pragma unroll
        for (int ks = 0; ks < 16; ks += 8) {
            uint32_t a[4][4], bb[4][2];
            #pragma unroll
            for (int mf = 0; mf < 4; mf++) {
                int r = wm * 64 + mf * 16;
                a[mf][0] = As[(r + lr    ) * SP + ks + lq];
                a[mf][1] = As[(r + lr + 8) * SP + ks + lq];
                a[mf][2] = As[(r + lr    ) * SP + ks + lq + 4];
                a[mf][3] = As[(r + lr + 8) * SP + ks + lq + 4];
            }
            #pragma unroll
            for (int nf = 0; nf < 4; nf++) {
                int cdx = wn * 32 + nf * 8;
                bb[nf][0] = Bs[(cdx + lr) * SP + ks + lq];
                bb[nf][1] = Bs[(cdx + lr) * SP + ks + lq + 4];
            }
            #pragma unroll
            for (int mf = 0; mf < 4; mf++)
                #pragma unroll
                for (int nf = 0; nf < 4; nf++)
                    mma8(acc[mf][nf], a[mf], bb[nf]);
        }
        if (c + 2 < nch) G_ISSUE(c + 2);
    }

    // epilogue: coalesced float2 + bias
    #pragma unroll
    for (int mf = 0; mf < 4; mf++) {
        int rr0 = bm + wm * 64 + mf * 16 + lr;
        #pragma unroll
        for (int nf = 0; nf < 4; nf++) {
            int cc = bn + wn * 32 + nf * 8 + 2 * lq;
            float bx = bias[cc], by = bias[cc + 1];
            *(float2*)&Cp[(size_t)rr0 * Nn + cc] =
                make_float2(acc[mf][nf][0] + bx, acc[mf][nf][1] + by);
            *(float2*)&Cp[(size_t)(rr0 + 8) * Nn + cc] =
                make_float2(acc[mf][nf][2] + bx, acc[mf][nf][3] + by);
        }
    }
}

// ============================================================
// Fused flash attention, tf32 MMA, register-resident softmax.
// grid = (N/64, H, B); 256 threads (8 warps); 64q x 64k tiles.
// K and V double-buffered cp.async. 3 barriers per tile.
// ============================================================
#define SK 68
#define SV 72
#define SS 68
#define ATT_SM_FLOATS (64*SK + 2*64*SK + 2*64*SV + 64*SS + 64*8)
#define ATT_SM_BYTES  (ATT_SM_FLOATS * 4)   // 108,544 -> 2 CTAs/SM

__global__ __launch_bounds__(256, 2) void attn_kernel(
    const float* __restrict__ alibi)
{
    extern __shared__ float sm[];
    uint32_t* Qs = (uint32_t*)sm;           // [64][SK] tf32, pre-scaled
    float* Kf   = sm + 64 * SK;             // [2][64][SK] raw f32
    float* Vf   = Kf + 2 * 64 * SK;         // [2][64][SV] raw f32
    float* Ss   = Vf + 2 * 64 * SV;         // [64][SS] tf32 prob bits
    float* red  = Ss + 64 * SS;             // [64][8]: max[0..3], sum[4..7]

    const int tid = threadIdx.x, lane = tid & 31, w = tid >> 5;
    const int wm = w >> 2, wn = w & 3;      // 2 x 4
    const int lr = lane >> 2, lq = lane & 3;
    const int qt = blockIdx.x, h = blockIdx.y, b = blockIdx.z;
    const int q0 = qt * 64;
    const int rm = wm * 32, cn = wn * 16;

    const int ldrow = tid >> 4;             // 0..15
    const int ldcol = (tid & 15) * 4;       // 0..60

    const float* Qg = g_qkv + (size_t)(b * NN + q0) * QKVW + h * 64;
    const float* Kbase = g_qkv + (size_t)(b * NN) * QKVW + CC + h * 64;
    const float* Vbase = g_qkv + (size_t)(b * NN) * QKVW + 2 * CC + h * 64;

    // ---- load Q (scale + tf32) ----
    #pragma unroll
    for (int it = 0; it < 4; it++) {
        int row = ldrow + it * 16;
        float4 v = *(const float4*)(Qg + (size_t)row * QKVW + ldcol);
        *(uint4*)&Qs[row * SK + ldcol] =
            make_uint4(f2tf(v.x * 0.125f), f2tf(v.y * 0.125f),
                       f2tf(v.z * 0.125f), f2tf(v.w * 0.125f));
    }

    // ---- prefetch K(0), V(0) (separate groups) ----
    #pragma unroll
    for (int it = 0; it < 4; it++) {
        int row = ldrow + it * 16;
        cpa16(&Kf[row * SK + ldcol], Kbase + (size_t)row * QKVW + ldcol);
    }
    CP_COMMIT();
    #pragma unroll
    for (int it = 0; it < 4; it++) {
        int row = ldrow + it * 16;
        cpa16(&Vf[row * SV + ldcol], Vbase + (size_t)row * QKVW + ldcol);
    }
    CP_COMMIT();

    float oacc[2][2][4];
    #pragma unroll
    for (int i = 0; i < 2; i++)
        #pragma unroll
        for (int j = 0; j < 2; j++)
            #pragma unroll
            for (int e = 0; e < 4; e++) oacc[i][j][e] = 0.f;
    float mrow_r[2][2] = {{-1e30f, -1e30f}, {-1e30f, -1e30f}};
    float lrow_r[2][2] = {{0.f, 0.f}, {0.f, 0.f}};

    const size_t abase = ((size_t)(b * HH + h) * NN + q0) * NN;

    for (int kt = 0; kt < 32; kt++) {
        const int kc0 = kt * 64;
        CP_WAIT(1);        // K(kt) landed (V(kt) may be pending)
        __syncthreads();   // S1: K visible; prev PV reads done

        // alibi + mask to regs
        float2 al[2][2][2];
        unsigned short mk[2];
        #pragma unroll
        for (int mf = 0; mf < 2; mf++) {
            int q = rm + mf * 16 + lr;
            #pragma unroll
            for (int nf = 0; nf < 2; nf++) {
                int c = cn + nf * 8 + 2 * lq;
                al[mf][nf][0] = *(const float2*)(alibi + abase + (size_t)q * NN + kc0 + c);
                al[mf][nf][1] = *(const float2*)(alibi + abase + (size_t)(q + 8) * NN + kc0 + c);
            }
        }
        #pragma unroll
        for (int nf = 0; nf < 2; nf++)
            mk[nf] = *(const unsigned short*)&g_mask[b * NN + kc0 + cn + nf * 8 + 2 * lq];

        // ---- S = Q @ K^T ----
        const float* Kb = Kf + (kt & 1) * 64 * SK;
        float sacc[2][2][4];
        #pragma unroll
        for (int i = 0; i < 2; i++)
            #pragma unroll
            for (int j = 0; j < 2; j++)
                #pragma unroll
                for (int e = 0; e < 4; e++) sacc[i][j][e] = 0.f;

        #pragma unroll
        for (int kc = 0; kc < 64; kc += 8) {
            uint32_t a[2][4], bf[2][2];
            #pragma unroll
            for (int mf = 0; mf < 2; mf++) {
                int r = rm + mf * 16;
                a[mf][0] = Qs[(r + lr    ) * SK + kc + lq];
                a[mf][1] = Qs[(r + lr + 8) * SK + kc + lq];
                a[mf][2] = Qs[(r + lr    ) * SK + kc + lq + 4];
                a[mf][3] = Qs[(r + lr + 8) * SK + kc + lq + 4];
            }
            #pragma unroll
            for (int nf = 0; nf < 2; nf++) {
                int c = cn + nf * 8;
                bf[nf][0] = f2tf(Kb[(c + lr) * SK + kc + lq]);
                bf[nf][1] = f2tf(Kb[(c + lr) * SK + kc + lq + 4]);
            }
            #pragma unroll
            for (int mf = 0; mf < 2; mf++)
                #pragma unroll
                for (int nf = 0; nf < 2; nf++)
                    mma8(sacc[mf][nf], a[mf], bf[nf]);
        }

        // issue K(kt+1), V(kt+1)
        if (kt < 31) {
            float* Kn = Kf + ((kt + 1) & 1) * 64 * SK;
            #pragma unroll
            for (int it = 0; it < 4; it++) {
                int row = ldrow + it * 16;
                cpa16(&Kn[row * SK + ldcol],
                      Kbase + (size_t)(kc0 + 64 + row) * QKVW + ldcol);
            }
            CP_COMMIT();
            float* Vn = Vf + ((kt + 1) & 1) * 64 * SV;
            #pragma unroll
            for (int it = 0; it < 4; it++) {
                int row = ldrow + it * 16;
                cpa16(&Vn[row * SV + ldcol],
                      Vbase + (size_t)(kc0 + 64 + row) * QKVW + ldcol);
            }
            CP_COMMIT();
        }

        // ---- fold alibi + mask into sacc ----
        #pragma unroll
        for (int mf = 0; mf < 2; mf++) {
            #pragma unroll
            for (int nf = 0; nf < 2; nf++) {
                bool m0 = (mk[nf] & 0xFF) != 0;
                bool m1 = (mk[nf] >> 8) != 0;
                sacc[mf][nf][0] = m0 ? -1e30f : sacc[mf][nf][0] + al[mf][nf][0].x;
                sacc[mf][nf][1] = m1 ? -1e30f : sacc[mf][nf][1] + al[mf][nf][0].y;
                sacc[mf][nf][2] = m0 ? -1e30f : sacc[mf][nf][2] + al[mf][nf][1].x;
                sacc[mf][nf][3] = m1 ? -1e30f : sacc[mf][nf][3] + al[mf][nf][1].y;
            }
        }

        // ---- per-row tile max: quad shfl + cross-warp partials ----
        #pragma unroll
        for (int mf = 0; mf < 2; mf++) {
            #pragma unroll
            for (int hh = 0; hh < 2; hh++) {
                float pm = fmaxf(fmaxf(sacc[mf][0][hh*2], sacc[mf][0][hh*2+1]),
                                 fmaxf(sacc[mf][1][hh*2], sacc[mf][1][hh*2+1]));
                pm = fmaxf(pm, __shfl_xor_sync(0xffffffffu, pm, 1));
                pm = fmaxf(pm, __shfl_xor_sync(0xffffffffu, pm, 2));
                if (lq == 0) red[(rm + mf * 16 + lr + hh * 8) * 8 + wn] = pm;
            }
        }

        if (kt < 31) { CP_WAIT(2); } else { CP_WAIT(0); }  // V(kt) landed
        __syncthreads();   // S2: partial maxes + V visible

        // ---- softmax in registers; write tf32 probs + partial sums ----
        float fac[2][2];
        #pragma unroll
        for (int mf = 0; mf < 2; mf++) {
            #pragma unroll
            for (int hh = 0; hh < 2; hh++) {
                int r = rm + mf * 16 + lr + hh * 8;
                float rmx = fmaxf(fmaxf(red[r*8+0], red[r*8+1]),
                                  fmaxf(red[r*8+2], red[r*8+3]));
                float mnew = fmaxf(mrow_r[mf][hh], rmx);
                fac[mf][hh] = __expf(mrow_r[mf][hh] - mnew);
                mrow_r[mf][hh] = mnew;
                float p00 = __expf(sacc[mf][0][hh*2]   - mnew);
                float p01 = __expf(sacc[mf][0][hh*2+1] - mnew);
                float p10 = __expf(sacc[mf][1][hh*2]   - mnew);
                float p11 = __expf(sacc[mf][1][hh*2+1] - mnew);
                float part = (p00 + p01) + (p10 + p11);
                part += __shfl_xor_sync(0xffffffffu, part, 1);
                part += __shfl_xor_sync(0xffffffffu, part, 2);
                if (lq == 0) red[r * 8 + 4 + wn] = part;
                *(float2*)&Ss[r * SS + cn + 2 * lq] =
                    make_float2(__uint_as_float(f2tf(p00)), __uint_as_float(f2tf(p01)));
                *(float2*)&Ss[r * SS + cn + 8 + 2 * lq] =
                    make_float2(__uint_as_float(f2tf(p10)), __uint_as_float(f2tf(p11)));
                #pragma unroll
                for (int nf = 0; nf < 2; nf++) {
                    oacc[mf][nf][hh*2]   *= fac[mf][hh];
                    oacc[mf][nf][hh*2+1] *= fac[mf][hh];
                }
            }
        }
        __syncthreads();   // S3: probs + partial sums visible

        // ---- l update + O += P @ V ----
        #pragma unroll
        for (int mf = 0; mf < 2; mf++) {
            #pragma unroll
            for (int hh = 0; hh < 2; hh++) {
                int r = rm + mf * 16 + lr + hh * 8;
                float ssum = (red[r*8+4] + red[r*8+5]) + (red[r*8+6] + red[r*8+7]);
                lrow_r[mf][hh] = lrow_r[mf][hh] * fac[mf][hh] + ssum;
            }
        }
        const float* Vb = Vf + (kt & 1) * 64 * SV;
        #pragma unroll
        for (int kc = 0; kc < 64; kc += 8) {
            uint32_t a[2][4], bf[2][2];
            #pragma unroll
            for (int mf = 0; mf < 2; mf++) {
                int r = rm + mf * 16;
                a[mf][0] = __float_as_uint(Ss[(r + lr    ) * SS + kc + lq]);
                a[mf][1] = __float_as_uint(Ss[(r + lr + 8) * SS + kc + lq]);
                a[mf][2] = __float_as_uint(Ss[(r + lr    ) * SS + kc + lq + 4]);
                a[mf][3] = __float_as_uint(Ss[(r + lr + 8) * SS + kc + lq + 4]);
            }
            #pragma unroll
            for (int nf = 0; nf < 2; nf++) {
                int c = cn + nf * 8;
                bf[nf][0] = f2tf(Vb[(kc + lq    ) * SV + c + lr]);
                bf[nf][1] = f2tf(Vb[(kc + lq + 4) * SV + c + lr]);
            }
            #pragma unroll
            for (int mf = 0; mf < 2; mf++)
                #pragma unroll
                for (int nf = 0; nf < 2; nf++)
                    mma8(oacc[mf][nf], a[mf], bf[nf]);
        }
    }

    // ---- normalize, tf32-round, write [B,N,H,D] ----
    #pragma unroll
    for (int mf = 0; mf < 2; mf++) {
        int q = rm + mf * 16 + lr;
        float inv0 = 1.0f / lrow_r[mf][0];
        float inv1 = 1.0f / lrow_r[mf][1];
        #pragma unroll
        for (int nf = 0; nf < 2; nf++) {
            int c = cn + nf * 8 + 2 * lq;
            size_t o0 = ((size_t)(b * NN + q0 + q) * HH + h) * DD + c;
            size_t o1 = ((size_t)(b * NN + q0 + q + 8) * HH + h) * DD + c;
            *(uint2*)&g_attn[o0] = make_uint2(f2tf(oacc[mf][nf][0] * inv0),
                                              f2tf(oacc[mf][nf][1] * inv0));
            *(uint2*)&g_attn[o1] = make_uint2(f2tf(oacc[mf][nf][2] * inv1),
                                              f2tf(oacc[mf][nf][3] * inv1));
        }
    }
}

extern "C" void kernel_launch(void* const* d_in, const int* in_sizes, int n_in,
                              void* d_out, int out_size)
{
    const float* x      = nullptr;
    const void*  pmask  = nullptr;
    const float* alibi  = nullptr;
    const float* qkv_w  = nullptr;
    const float* qkv_b  = nullptr;
    const float* proj_w = nullptr;
    const float* proj_b = nullptr;
    for (int i = 0; i < n_in; i++) {
        switch (in_sizes[i]) {
            case 6291456:   x      = (const float*)d_in[i]; break;
            case 8192:      pmask  = d_in[i];               break;
            case 201326592: alibi  = (const float*)d_in[i]; break;
            case 1769472:   qkv_w  = (const float*)d_in[i]; break;
            case 2304:      qkv_b  = (const float*)d_in[i]; break;
            case 589824:    proj_w = (const float*)d_in[i]; break;
            case 768:       proj_b = (const float*)d_in[i]; break;
        }
    }
    float* out = (float*)d_out;

    cudaFuncSetAttribute(attn_kernel,
                         cudaFuncAttributeMaxDynamicSharedMemorySize, ATT_SM_BYTES);
    cudaFuncSetAttribute(gemm_tc<0>,
                         cudaFuncAttributeMaxDynamicSharedMemorySize, GEMM_SM_BYTES);
    cudaFuncSetAttribute(gemm_tc<1>,
                         cudaFuncAttributeMaxDynamicSharedMemorySize, GEMM_SM_BYTES);

    mask_conv_kernel<<<1, 1024>>>(pmask);
    conv_x_kernel<<<6144, 256>>>(x);

    // 1) qkv_w^T (tf32) ; QKV projection -> g_qkv
    transpose_k<<<dim3(QKVW / 32, CC / 32), dim3(32, 8)>>>(qkv_w, CC, QKVW);
    gemm_tc<0><<<dim3(QKVW / 128, (BB * NN) / 128), 256, GEMM_SM_BYTES>>>(
        qkv_b, nullptr, CC, QKVW);

    // 2) fused attention (writes tf32-rounded g_attn)
    attn_kernel<<<dim3(NN / 64, HH, BB), 256, ATT_SM_BYTES>>>(alibi);

    // 3) proj_w^T (tf32) ; output projection -> d_out
    transpose_k<<<dim3(CC / 32, CC / 32), dim3(32, 8)>>>(proj_w, CC, CC);
    gemm_tc<1><<<dim3(CC / 128, (BB * NN) / 128), 256, GEMM_SM_BYTES>>>(
        proj_b, out, CC, CC);
}